// round 1
// baseline (speedup 1.0000x reference)
#include <cuda_runtime.h>
#include <math.h>

#define B_  2
#define S_  2048
#define D_  1024
#define H_  16
#define HD_ 64
#define M_  (B_*S_)        // 4096 rows

// Scratch (allocation-free rule: __device__ globals)
__device__ float g_q[B_*H_*S_*HD_];    // [B,H,S,HD] 16MB
__device__ float g_k[B_*H_*S_*HD_];
__device__ float g_v[B_*H_*S_*HD_];
__device__ float g_ao[M_*D_];          // attention out, [B,S,D]

// ---------------------------------------------------------------------------
// Tiled SGEMM: C[M,N] = A[M,K] @ W[K,N] + bias, with epilogue variants.
// MODE 0: A = g_ao, write plain row-major to Cout (final output projection)
// MODE 1/2/3: A = Ain (x), scatter into g_q/g_k/g_v as [B,H,S,HD]
// BM=BN=128, BK=8, 256 threads, 8x8 per thread.
// ---------------------------------------------------------------------------
template<int MODE>
__global__ void __launch_bounds__(256)
gemm_bias(const float* __restrict__ Ain, const float* __restrict__ W,
          const float* __restrict__ bias, float* __restrict__ Cout)
{
    constexpr int K = D_;
    constexpr int N = D_;
    const float* A = (MODE == 0) ? (const float*)g_ao : Ain;

    __shared__ float As[8][132];   // transposed A tile, padded
    __shared__ float Bs[8][132];   // B tile, padded

    const int tid  = threadIdx.x;
    const int tr   = tid >> 4;     // 0..15  (8 output rows each)
    const int tc   = tid & 15;     // 0..15  (8 output cols each)
    const int rowA = tid >> 1;     // 0..127
    const int colA = tid & 1;      // 0..1 (float4)
    const int rowB = tid >> 5;     // 0..7
    const int colB = tid & 31;     // 0..31 (float4)
    const int bM = blockIdx.y * 128;
    const int bN = blockIdx.x * 128;

    const float* Ap = A + (size_t)(bM + rowA) * K + colA * 4;
    const float* Bp = W + (size_t)rowB * N + bN + colB * 4;

    float acc[8][8];
#pragma unroll
    for (int i = 0; i < 8; i++)
#pragma unroll
        for (int j = 0; j < 8; j++) acc[i][j] = 0.f;

    for (int k0 = 0; k0 < K; k0 += 8) {
        float4 a4 = *(const float4*)(Ap + k0);
        As[colA*4+0][rowA] = a4.x;
        As[colA*4+1][rowA] = a4.y;
        As[colA*4+2][rowA] = a4.z;
        As[colA*4+3][rowA] = a4.w;
        float4 b4 = *(const float4*)(Bp + (size_t)k0 * N);
        *(float4*)&Bs[rowB][colB*4] = b4;
        __syncthreads();

#pragma unroll
        for (int k = 0; k < 8; k++) {
            float regM[8], regN[8];
            *(float4*)&regM[0] = *(const float4*)&As[k][tr*8];
            *(float4*)&regM[4] = *(const float4*)&As[k][tr*8+4];
            *(float4*)&regN[0] = *(const float4*)&Bs[k][tc*8];
            *(float4*)&regN[4] = *(const float4*)&Bs[k][tc*8+4];
#pragma unroll
            for (int i = 0; i < 8; i++)
#pragma unroll
                for (int j = 0; j < 8; j++)
                    acc[i][j] = fmaf(regM[i], regN[j], acc[i][j]);
        }
        __syncthreads();
    }

    if (MODE == 0) {
#pragma unroll
        for (int i = 0; i < 8; i++) {
            int m = bM + tr*8 + i;
            float* dst = Cout + (size_t)m * N + bN + tc*8;
#pragma unroll
            for (int j = 0; j < 8; j++)
                dst[j] = acc[i][j] + bias[bN + tc*8 + j];
        }
    } else {
        float* G = (MODE == 1) ? g_q : (MODE == 2) ? g_k : g_v;
#pragma unroll
        for (int i = 0; i < 8; i++) {
            int m = bM + tr*8 + i;
            int b = m >> 11;            // m / 2048
            int s = m & (S_ - 1);
#pragma unroll
            for (int j = 0; j < 8; j++) {
                int n  = bN + tc*8 + j;
                int h  = n >> 6;
                int hd = n & 63;
                G[(((size_t)(b*H_ + h) * S_ + s) << 6) + hd] = acc[i][j] + bias[n];
            }
        }
    }
}

// ---------------------------------------------------------------------------
// Flash-attention style kernel. Block = 64 queries of one (b,h).
// 256 threads: tx = tid%16 (4 cols each), ty = tid/16 (4 q-rows each).
// Q,K stored transposed in smem (d-major) so score frags are float4 loads.
// Online softmax with per-thread m/l for its 4 rows; P staged via smem for PV.
// ---------------------------------------------------------------------------
#define SMEM_ATTN ((2*64*68 + 2*64*64) * 4)   // 67584 bytes

__global__ void __launch_bounds__(256)
attn_kernel()
{
    extern __shared__ float sm[];
    float* sQt = sm;                     // [64 d][68] (rows padded)
    float* sKt = sm + 64*68;             // [64 d][68]
    float* sV  = sm + 2*64*68;           // [64 k][64 d]
    float* sP  = sm + 2*64*68 + 64*64;   // [64 q][64 k]

    const int tid = threadIdx.x;
    const int tx  = tid & 15;
    const int ty  = tid >> 4;
    const int qt  = blockIdx.x;          // query tile 0..31
    const int bh  = blockIdx.y;          // 0..31

    const float* Qg = g_q + (size_t)bh * (S_*HD_) + (size_t)qt * 64 * HD_;
    const float* Kg = g_k + (size_t)bh * (S_*HD_);
    const float* Vg = g_v + (size_t)bh * (S_*HD_);

    // load Q tile transposed
#pragma unroll
    for (int it = 0; it < 4; it++) {
        int idx = it*256 + tid;
        int r = idx >> 4, c4 = idx & 15;
        float4 q4 = *(const float4*)(Qg + r*HD_ + c4*4);
        sQt[(c4*4+0)*68 + r] = q4.x;
        sQt[(c4*4+1)*68 + r] = q4.y;
        sQt[(c4*4+2)*68 + r] = q4.z;
        sQt[(c4*4+3)*68 + r] = q4.w;
    }

    float m_[4], l_[4], acc[4][4];
#pragma unroll
    for (int i = 0; i < 4; i++) {
        m_[i] = -1e30f; l_[i] = 0.f;
#pragma unroll
        for (int j = 0; j < 4; j++) acc[i][j] = 0.f;
    }
    __syncthreads();

    for (int jt = 0; jt < S_/64; jt++) {
        // load K (transposed) and V (natural) tiles
#pragma unroll
        for (int it = 0; it < 4; it++) {
            int idx = it*256 + tid;
            int r = idx >> 4, c4 = idx & 15;
            float4 k4 = *(const float4*)(Kg + (size_t)(jt*64 + r)*HD_ + c4*4);
            sKt[(c4*4+0)*68 + r] = k4.x;
            sKt[(c4*4+1)*68 + r] = k4.y;
            sKt[(c4*4+2)*68 + r] = k4.z;
            sKt[(c4*4+3)*68 + r] = k4.w;
            float4 v4 = *(const float4*)(Vg + (size_t)(jt*64 + r)*HD_ + c4*4);
            *(float4*)&sV[r*64 + c4*4] = v4;
        }
        __syncthreads();

        // scores: s[qi][kj] = sum_d Q[ty*4+qi][d] * K[tx*4+kj][d]
        float s[4][4];
#pragma unroll
        for (int i = 0; i < 4; i++)
#pragma unroll
            for (int j = 0; j < 4; j++) s[i][j] = 0.f;

#pragma unroll 8
        for (int d = 0; d < 64; d++) {
            float4 q4 = *(const float4*)&sQt[d*68 + ty*4];
            float4 k4 = *(const float4*)&sKt[d*68 + tx*4];
            float qa[4] = {q4.x, q4.y, q4.z, q4.w};
            float ka[4] = {k4.x, k4.y, k4.z, k4.w};
#pragma unroll
            for (int i = 0; i < 4; i++)
#pragma unroll
                for (int j = 0; j < 4; j++)
                    s[i][j] = fmaf(qa[i], ka[j], s[i][j]);
        }

        const float sc = 0.125f;   // 1/sqrt(64)
#pragma unroll
        for (int qi = 0; qi < 4; qi++) {
            float s0 = s[qi][0]*sc, s1 = s[qi][1]*sc, s2 = s[qi][2]*sc, s3 = s[qi][3]*sc;
            float rm = fmaxf(fmaxf(s0, s1), fmaxf(s2, s3));
#pragma unroll
            for (int off = 8; off >= 1; off >>= 1)
                rm = fmaxf(rm, __shfl_xor_sync(0xffffffffu, rm, off));
            float mn   = fmaxf(m_[qi], rm);
            float corr = __expf(m_[qi] - mn);
            float p0 = __expf(s0 - mn), p1 = __expf(s1 - mn);
            float p2 = __expf(s2 - mn), p3 = __expf(s3 - mn);
            float rs = (p0 + p1) + (p2 + p3);
#pragma unroll
            for (int off = 8; off >= 1; off >>= 1)
                rs += __shfl_xor_sync(0xffffffffu, rs, off);
            l_[qi] = l_[qi]*corr + rs;
            m_[qi] = mn;
            acc[qi][0] *= corr; acc[qi][1] *= corr;
            acc[qi][2] *= corr; acc[qi][3] *= corr;
            *(float4*)&sP[(ty*4+qi)*64 + tx*4] = make_float4(p0, p1, p2, p3);
        }
        __syncthreads();

        // O += P @ V   (thread: rows ty*4.., d-cols tx*4..)
#pragma unroll 8
        for (int kk = 0; kk < 64; kk++) {
            float4 v4 = *(const float4*)&sV[kk*64 + tx*4];
#pragma unroll
            for (int qi = 0; qi < 4; qi++) {
                float p = sP[(ty*4+qi)*64 + kk];
                acc[qi][0] = fmaf(p, v4.x, acc[qi][0]);
                acc[qi][1] = fmaf(p, v4.y, acc[qi][1]);
                acc[qi][2] = fmaf(p, v4.z, acc[qi][2]);
                acc[qi][3] = fmaf(p, v4.w, acc[qi][3]);
            }
        }
        __syncthreads();
    }

    // epilogue: write [B,S,D] for the final projection
    const int b = bh >> 4, h = bh & 15;
#pragma unroll
    for (int qi = 0; qi < 4; qi++) {
        int q = qt*64 + ty*4 + qi;
        float inv = 1.f / l_[qi];
        float4 o = make_float4(acc[qi][0]*inv, acc[qi][1]*inv,
                               acc[qi][2]*inv, acc[qi][3]*inv);
        *(float4*)(g_ao + (size_t)(b*S_ + q)*D_ + h*HD_ + tx*4) = o;
    }
}

// ---------------------------------------------------------------------------

extern "C" void kernel_launch(void* const* d_in, const int* in_sizes, int n_in,
                              void* d_out, int out_size)
{
    const float* x  = (const float*)d_in[0];
    const float* Wq = (const float*)d_in[1];
    const float* bq = (const float*)d_in[2];
    const float* Wk = (const float*)d_in[3];
    const float* bk = (const float*)d_in[4];
    const float* Wv = (const float*)d_in[5];
    const float* bv = (const float*)d_in[6];
    const float* Wo = (const float*)d_in[7];
    const float* bo = (const float*)d_in[8];
    float* out = (float*)d_out;

    cudaFuncSetAttribute(attn_kernel,
                         cudaFuncAttributeMaxDynamicSharedMemorySize, SMEM_ATTN);

    dim3 gg(D_/128, M_/128);
    gemm_bias<1><<<gg, 256>>>(x, Wq, bq, nullptr);
    gemm_bias<2><<<gg, 256>>>(x, Wk, bk, nullptr);
    gemm_bias<3><<<gg, 256>>>(x, Wv, bv, nullptr);
    attn_kernel<<<dim3(S_/64, B_*H_), 256, SMEM_ATTN>>>();
    gemm_bias<0><<<gg, 256>>>(nullptr, Wo, bo, out);
}

// round 4
// speedup vs baseline: 1.3418x; 1.3418x over previous
#include <cuda_runtime.h>
#include <cuda_bf16.h>
#include <stdint.h>
#include <math.h>

#define B_  2
#define S_  2048
#define D_  1024
#define H_  16
#define HD_ 64
#define M_  (B_*S_)        // 4096 rows

// ---------------------------------------------------------------------------
// Scratch (__device__ globals; no allocs allowed)
// ---------------------------------------------------------------------------
__device__ float g_q[B_*H_*S_*HD_];    // [B,H,S,HD]
__device__ float g_k[B_*H_*S_*HD_];
__device__ float g_v[B_*H_*S_*HD_];
__device__ float g_ao[M_*D_];          // attention out, [B,S,D]

__device__ __nv_bfloat16 g_xhi[M_*D_],  g_xlo[M_*D_];      // x split, [M,K]
__device__ __nv_bfloat16 g_aohi[M_*D_], g_aolo[M_*D_];     // attn-out split
__device__ __nv_bfloat16 g_whi[4][D_*D_], g_wlo[4][D_*D_]; // W^T splits, [N,K]

// ---------------------------------------------------------------------------
// mma.sync m16n8k16 bf16 (baseline PTX; works on compute_103)
// ---------------------------------------------------------------------------
__device__ __forceinline__ void mma16816(float* c, const uint32_t* a, const uint32_t* b)
{
    asm volatile("mma.sync.aligned.m16n8k16.row.col.f32.bf16.bf16.f32 "
        "{%0,%1,%2,%3}, {%4,%5,%6,%7}, {%8,%9}, {%0,%1,%2,%3};"
        : "+f"(c[0]), "+f"(c[1]), "+f"(c[2]), "+f"(c[3])
        : "r"(a[0]), "r"(a[1]), "r"(a[2]), "r"(a[3]), "r"(b[0]), "r"(b[1]));
}

// ---------------------------------------------------------------------------
// Split kernels: fp32 -> bf16 hi + bf16 lo (residual)
// ---------------------------------------------------------------------------
__global__ void split_plain(const float* __restrict__ in, __nv_bfloat16* __restrict__ hi,
                            __nv_bfloat16* __restrict__ lo, int n4)
{
    int i = blockIdx.x * blockDim.x + threadIdx.x;
    if (i >= n4) return;
    float4 a = ((const float4*)in)[i];
    __nv_bfloat16 h0 = __float2bfloat16_rn(a.x), h1 = __float2bfloat16_rn(a.y);
    __nv_bfloat16 h2 = __float2bfloat16_rn(a.z), h3 = __float2bfloat16_rn(a.w);
    __nv_bfloat16 l0 = __float2bfloat16_rn(a.x - __bfloat162float(h0));
    __nv_bfloat16 l1 = __float2bfloat16_rn(a.y - __bfloat162float(h1));
    __nv_bfloat16 l2 = __float2bfloat16_rn(a.z - __bfloat162float(h2));
    __nv_bfloat16 l3 = __float2bfloat16_rn(a.w - __bfloat162float(h3));
    ((__nv_bfloat162*)hi)[2*i]   = __nv_bfloat162(h0, h1);
    ((__nv_bfloat162*)hi)[2*i+1] = __nv_bfloat162(h2, h3);
    ((__nv_bfloat162*)lo)[2*i]   = __nv_bfloat162(l0, l1);
    ((__nv_bfloat162*)lo)[2*i+1] = __nv_bfloat162(l2, l3);
}

// W [K,N] fp32 -> W^T [N,K] bf16 hi/lo  (32x32 smem tile transpose)
__global__ void split_transpose(const float* __restrict__ in, __nv_bfloat16* __restrict__ hi,
                                __nv_bfloat16* __restrict__ lo)
{
    __shared__ float t[32][33];
    const int k0 = blockIdx.y * 32, n0 = blockIdx.x * 32;
    const int tx = threadIdx.x, ty = threadIdx.y;   // 32 x 8
#pragma unroll
    for (int i = 0; i < 32; i += 8)
        t[ty + i][tx] = in[(size_t)(k0 + ty + i) * D_ + n0 + tx];
    __syncthreads();
#pragma unroll
    for (int i = 0; i < 32; i += 8) {
        float a = t[tx][ty + i];   // = in[k0+tx][n0+ty+i]
        __nv_bfloat16 h = __float2bfloat16_rn(a);
        __nv_bfloat16 l = __float2bfloat16_rn(a - __bfloat162float(h));
        hi[(size_t)(n0 + ty + i) * D_ + k0 + tx] = h;
        lo[(size_t)(n0 + ty + i) * D_ + k0 + tx] = l;
    }
}

// ---------------------------------------------------------------------------
// HMMA GEMM: C[128x128] = A[M,K] x B[N,K]^T with hi/lo split (3-phase K loop).
// 256 threads = 8 warps (2 m x 4 n), warp tile 64x32, mma m16n8k16 bf16.
// Double-buffered smem, padded stride 40 (conflict-free LDS.32 frags).
// FIX vs r3: full BK=32 staging — each thread does TWO uint4 loads per matrix
// (columns half*8 + {0,16}); previously only k[0:16) was written -> NaN.
// MODE 0: write Cout + bias.  MODE 1/2/3: scatter to g_q/g_k/g_v as [B,H,S,HD].
// ---------------------------------------------------------------------------
#define BK   32
#define LDS_ 40
#define NKIT 96   // 3 phases x (1024/32)

template<int MODE>
__global__ void __launch_bounds__(256, 2)
gemm_tc(const __nv_bfloat16* __restrict__ Ahi, const __nv_bfloat16* __restrict__ Alo,
        const __nv_bfloat16* __restrict__ Bhi, const __nv_bfloat16* __restrict__ Blo,
        const float* __restrict__ bias, float* __restrict__ Cout)
{
    __shared__ __nv_bfloat16 sA[2][128][LDS_];
    __shared__ __nv_bfloat16 sB[2][128][LDS_];

    const int tid  = threadIdx.x;
    const int wid  = tid >> 5, lane = tid & 31;
    const int g    = lane >> 2, t4 = lane & 3;
    const int wm   = (wid >> 2) * 64;     // warp m offset (0,64)
    const int wn   = (wid & 3) * 32;      // warp n offset (0,32,64,96)
    const int bM   = blockIdx.y * 128, bN = blockIdx.x * 128;

    const int rowL = tid >> 1;            // 0..127 load row
    const int colL = (tid & 1) * 8;       // base col: 0 or 8; +16 on 2nd load
    const size_t aRow = (size_t)(bM + rowL) * D_;
    const size_t bRow = (size_t)(bN + rowL) * D_;

    float acc[4][4][4];
#pragma unroll
    for (int mi = 0; mi < 4; mi++)
#pragma unroll
        for (int ni = 0; ni < 4; ni++)
#pragma unroll
            for (int r = 0; r < 4; r++) acc[mi][ni][r] = 0.f;

    auto srcA = [&](int kc) { return (kc < 64) ? Ahi : Alo; };
    auto srcB = [&](int kc) { return (kc >= 32 && kc < 64) ? Blo : Bhi; };
    auto koff = [&](int kc) { return (size_t)(kc & 31) * 32; };

    // prologue: stage 0 into buffer 0
    {
        const __nv_bfloat16* A = srcA(0);
        const __nv_bfloat16* Bp = srcB(0);
        const size_t k0 = koff(0);
#pragma unroll
        for (int it = 0; it < 2; it++) {
            const int c = colL + it * 16;
            *(uint4*)&sA[0][rowL][c] = *(const uint4*)(A  + aRow + k0 + c);
            *(uint4*)&sB[0][rowL][c] = *(const uint4*)(Bp + bRow + k0 + c);
        }
    }
    __syncthreads();

    for (int kc = 0; kc < NKIT; kc++) {
        const int cur = kc & 1, nxt = cur ^ 1;
        uint4 ra[2], rb[2];
        const bool more = (kc + 1 < NKIT);
        if (more) {
            const __nv_bfloat16* A = srcA(kc + 1);
            const __nv_bfloat16* Bp = srcB(kc + 1);
            const size_t k0 = koff(kc + 1);
#pragma unroll
            for (int it = 0; it < 2; it++) {
                const int c = colL + it * 16;
                ra[it] = *(const uint4*)(A  + aRow + k0 + c);
                rb[it] = *(const uint4*)(Bp + bRow + k0 + c);
            }
        }

#pragma unroll
        for (int ks = 0; ks < 2; ks++) {
            const int k0 = ks * 16;
            uint32_t af[4][4];
#pragma unroll
            for (int mi = 0; mi < 4; mi++) {
                const int r0 = wm + mi * 16 + g;
                af[mi][0] = *(const uint32_t*)&sA[cur][r0    ][k0 + t4 * 2];
                af[mi][1] = *(const uint32_t*)&sA[cur][r0 + 8][k0 + t4 * 2];
                af[mi][2] = *(const uint32_t*)&sA[cur][r0    ][k0 + 8 + t4 * 2];
                af[mi][3] = *(const uint32_t*)&sA[cur][r0 + 8][k0 + 8 + t4 * 2];
            }
            uint32_t bf[4][2];
#pragma unroll
            for (int ni = 0; ni < 4; ni++) {
                const int n = wn + ni * 8 + g;
                bf[ni][0] = *(const uint32_t*)&sB[cur][n][k0 + t4 * 2];
                bf[ni][1] = *(const uint32_t*)&sB[cur][n][k0 + 8 + t4 * 2];
            }
#pragma unroll
            for (int mi = 0; mi < 4; mi++)
#pragma unroll
                for (int ni = 0; ni < 4; ni++)
                    mma16816(acc[mi][ni], af[mi], bf[ni]);
        }

        if (more) {
#pragma unroll
            for (int it = 0; it < 2; it++) {
                const int c = colL + it * 16;
                *(uint4*)&sA[nxt][rowL][c] = ra[it];
                *(uint4*)&sB[nxt][rowL][c] = rb[it];
            }
        }
        __syncthreads();
    }

    // epilogue
#pragma unroll
    for (int mi = 0; mi < 4; mi++) {
#pragma unroll
        for (int hm = 0; hm < 2; hm++) {
            const int m = bM + wm + mi * 16 + g + hm * 8;
#pragma unroll
            for (int ni = 0; ni < 4; ni++) {
                const int n = bN + wn + ni * 8 + t4 * 2;
                const float v0 = acc[mi][ni][hm * 2 + 0] + bias[n];
                const float v1 = acc[mi][ni][hm * 2 + 1] + bias[n + 1];
                if (MODE == 0) {
                    *(float2*)(Cout + (size_t)m * D_ + n) = make_float2(v0, v1);
                } else {
                    float* G = (MODE == 1) ? g_q : (MODE == 2) ? g_k : g_v;
                    const int bb = m >> 11, ss = m & (S_ - 1);
                    const int h = n >> 6, hd = n & 63;
                    *(float2*)(G + (((size_t)(bb * H_ + h) * S_ + ss) << 6) + hd)
                        = make_float2(v0, v1);
                }
            }
        }
    }
}

// ---------------------------------------------------------------------------
// Flash-attention (fp32, unchanged from round 1)
// ---------------------------------------------------------------------------
#define SMEM_ATTN ((2*64*68 + 2*64*64) * 4)

__global__ void __launch_bounds__(256)
attn_kernel()
{
    extern __shared__ float sm[];
    float* sQt = sm;
    float* sKt = sm + 64*68;
    float* sV  = sm + 2*64*68;
    float* sP  = sm + 2*64*68 + 64*64;

    const int tid = threadIdx.x;
    const int tx  = tid & 15;
    const int ty  = tid >> 4;
    const int qt  = blockIdx.x;
    const int bh  = blockIdx.y;

    const float* Qg = g_q + (size_t)bh * (S_*HD_) + (size_t)qt * 64 * HD_;
    const float* Kg = g_k + (size_t)bh * (S_*HD_);
    const float* Vg = g_v + (size_t)bh * (S_*HD_);

#pragma unroll
    for (int it = 0; it < 4; it++) {
        int idx = it*256 + tid;
        int r = idx >> 4, c4 = idx & 15;
        float4 q4 = *(const float4*)(Qg + r*HD_ + c4*4);
        sQt[(c4*4+0)*68 + r] = q4.x;
        sQt[(c4*4+1)*68 + r] = q4.y;
        sQt[(c4*4+2)*68 + r] = q4.z;
        sQt[(c4*4+3)*68 + r] = q4.w;
    }

    float m_[4], l_[4], acc[4][4];
#pragma unroll
    for (int i = 0; i < 4; i++) {
        m_[i] = -1e30f; l_[i] = 0.f;
#pragma unroll
        for (int j = 0; j < 4; j++) acc[i][j] = 0.f;
    }
    __syncthreads();

    for (int jt = 0; jt < S_/64; jt++) {
#pragma unroll
        for (int it = 0; it < 4; it++) {
            int idx = it*256 + tid;
            int r = idx >> 4, c4 = idx & 15;
            float4 k4 = *(const float4*)(Kg + (size_t)(jt*64 + r)*HD_ + c4*4);
            sKt[(c4*4+0)*68 + r] = k4.x;
            sKt[(c4*4+1)*68 + r] = k4.y;
            sKt[(c4*4+2)*68 + r] = k4.z;
            sKt[(c4*4+3)*68 + r] = k4.w;
            float4 v4 = *(const float4*)(Vg + (size_t)(jt*64 + r)*HD_ + c4*4);
            *(float4*)&sV[r*64 + c4*4] = v4;
        }
        __syncthreads();

        float s[4][4];
#pragma unroll
        for (int i = 0; i < 4; i++)
#pragma unroll
            for (int j = 0; j < 4; j++) s[i][j] = 0.f;

#pragma unroll 8
        for (int d = 0; d < 64; d++) {
            float4 q4 = *(const float4*)&sQt[d*68 + ty*4];
            float4 k4 = *(const float4*)&sKt[d*68 + tx*4];
            float qa[4] = {q4.x, q4.y, q4.z, q4.w};
            float ka[4] = {k4.x, k4.y, k4.z, k4.w};
#pragma unroll
            for (int i = 0; i < 4; i++)
#pragma unroll
                for (int j = 0; j < 4; j++)
                    s[i][j] = fmaf(qa[i], ka[j], s[i][j]);
        }

        const float sc = 0.125f;
#pragma unroll
        for (int qi = 0; qi < 4; qi++) {
            float s0 = s[qi][0]*sc, s1 = s[qi][1]*sc, s2 = s[qi][2]*sc, s3 = s[qi][3]*sc;
            float rm = fmaxf(fmaxf(s0, s1), fmaxf(s2, s3));
#pragma unroll
            for (int off = 8; off >= 1; off >>= 1)
                rm = fmaxf(rm, __shfl_xor_sync(0xffffffffu, rm, off));
            float mn   = fmaxf(m_[qi], rm);
            float corr = __expf(m_[qi] - mn);
            float p0 = __expf(s0 - mn), p1 = __expf(s1 - mn);
            float p2 = __expf(s2 - mn), p3 = __expf(s3 - mn);
            float rs = (p0 + p1) + (p2 + p3);
#pragma unroll
            for (int off = 8; off >= 1; off >>= 1)
                rs += __shfl_xor_sync(0xffffffffu, rs, off);
            l_[qi] = l_[qi]*corr + rs;
            m_[qi] = mn;
            acc[qi][0] *= corr; acc[qi][1] *= corr;
            acc[qi][2] *= corr; acc[qi][3] *= corr;
            *(float4*)&sP[(ty*4+qi)*64 + tx*4] = make_float4(p0, p1, p2, p3);
        }
        __syncthreads();

#pragma unroll 8
        for (int kk = 0; kk < 64; kk++) {
            float4 v4 = *(const float4*)&sV[kk*64 + tx*4];
#pragma unroll
            for (int qi = 0; qi < 4; qi++) {
                float p = sP[(ty*4+qi)*64 + kk];
                acc[qi][0] = fmaf(p, v4.x, acc[qi][0]);
                acc[qi][1] = fmaf(p, v4.y, acc[qi][1]);
                acc[qi][2] = fmaf(p, v4.z, acc[qi][2]);
                acc[qi][3] = fmaf(p, v4.w, acc[qi][3]);
            }
        }
        __syncthreads();
    }

    const int b = bh >> 4, h = bh & 15;
#pragma unroll
    for (int qi = 0; qi < 4; qi++) {
        int q = qt*64 + ty*4 + qi;
        float inv = 1.f / l_[qi];
        float4 o = make_float4(acc[qi][0]*inv, acc[qi][1]*inv,
                               acc[qi][2]*inv, acc[qi][3]*inv);
        *(float4*)(g_ao + (size_t)(b*S_ + q)*D_ + h*HD_ + tx*4) = o;
    }
}

// ---------------------------------------------------------------------------

extern "C" void kernel_launch(void* const* d_in, const int* in_sizes, int n_in,
                              void* d_out, int out_size)
{
    const float* x  = (const float*)d_in[0];
    const float* Wq = (const float*)d_in[1];
    const float* bq = (const float*)d_in[2];
    const float* Wk = (const float*)d_in[3];
    const float* bk = (const float*)d_in[4];
    const float* Wv = (const float*)d_in[5];
    const float* bv = (const float*)d_in[6];
    const float* Wo = (const float*)d_in[7];
    const float* bo = (const float*)d_in[8];
    float* out = (float*)d_out;

    void *p_ao, *p_xhi, *p_xlo, *p_aohi, *p_aolo, *p_whi, *p_wlo;
    cudaGetSymbolAddress(&p_ao,   g_ao);
    cudaGetSymbolAddress(&p_xhi,  g_xhi);
    cudaGetSymbolAddress(&p_xlo,  g_xlo);
    cudaGetSymbolAddress(&p_aohi, g_aohi);
    cudaGetSymbolAddress(&p_aolo, g_aolo);
    cudaGetSymbolAddress(&p_whi,  g_whi);
    cudaGetSymbolAddress(&p_wlo,  g_wlo);
    __nv_bfloat16* xhi  = (__nv_bfloat16*)p_xhi;
    __nv_bfloat16* xlo  = (__nv_bfloat16*)p_xlo;
    __nv_bfloat16* aohi = (__nv_bfloat16*)p_aohi;
    __nv_bfloat16* aolo = (__nv_bfloat16*)p_aolo;
    __nv_bfloat16* whi  = (__nv_bfloat16*)p_whi;
    __nv_bfloat16* wlo  = (__nv_bfloat16*)p_wlo;

    cudaFuncSetAttribute(attn_kernel,
                         cudaFuncAttributeMaxDynamicSharedMemorySize, SMEM_ATTN);

    const int n4 = M_ * D_ / 4;
    dim3 tb(32, 8), tg(D_/32, D_/32);

    split_plain<<<(n4 + 255)/256, 256>>>(x, xhi, xlo, n4);
    split_transpose<<<tg, tb>>>(Wq, whi + 0*(size_t)D_*D_, wlo + 0*(size_t)D_*D_);
    split_transpose<<<tg, tb>>>(Wk, whi + 1*(size_t)D_*D_, wlo + 1*(size_t)D_*D_);
    split_transpose<<<tg, tb>>>(Wv, whi + 2*(size_t)D_*D_, wlo + 2*(size_t)D_*D_);
    split_transpose<<<tg, tb>>>(Wo, whi + 3*(size_t)D_*D_, wlo + 3*(size_t)D_*D_);

    dim3 gg(D_/128, M_/128);
    gemm_tc<1><<<gg, 256>>>(xhi, xlo, whi + 0*(size_t)D_*D_, wlo + 0*(size_t)D_*D_, bq, nullptr);
    gemm_tc<2><<<gg, 256>>>(xhi, xlo, whi + 1*(size_t)D_*D_, wlo + 1*(size_t)D_*D_, bk, nullptr);
    gemm_tc<3><<<gg, 256>>>(xhi, xlo, whi + 2*(size_t)D_*D_, wlo + 2*(size_t)D_*D_, bv, nullptr);

    attn_kernel<<<dim3(S_/64, B_*H_), 256, SMEM_ATTN>>>();

    split_plain<<<(n4 + 255)/256, 256>>>((const float*)p_ao, aohi, aolo, n4);
    gemm_tc<0><<<gg, 256>>>(aohi, aolo, whi + 3*(size_t)D_*D_, wlo + 3*(size_t)D_*D_, bo, out);
}

// round 5
// speedup vs baseline: 2.1967x; 1.6371x over previous
#include <cuda_runtime.h>
#include <cuda_bf16.h>
#include <stdint.h>
#include <math.h>

#define B_  2
#define S_  2048
#define D_  1024
#define H_  16
#define HD_ 64
#define M_  (B_*S_)        // 4096 rows

// ---------------------------------------------------------------------------
// Scratch (__device__ globals; no allocs allowed)
// ---------------------------------------------------------------------------
__device__ __nv_bfloat16 g_qhi[B_*H_*S_*HD_], g_qlo[B_*H_*S_*HD_];   // [B,H,S,HD]
__device__ __nv_bfloat16 g_khi[B_*H_*S_*HD_], g_klo[B_*H_*S_*HD_];
__device__ __nv_bfloat16 g_vhi[B_*H_*S_*HD_], g_vlo[B_*H_*S_*HD_];
__device__ __nv_bfloat16 g_aohi[M_*D_], g_aolo[M_*D_];               // [B,S,D]
__device__ __nv_bfloat16 g_xhi[M_*D_],  g_xlo[M_*D_];                // x split
__device__ __nv_bfloat16 g_whi[4][D_*D_], g_wlo[4][D_*D_];           // W^T splits

// ---------------------------------------------------------------------------
// mma.sync m16n8k16 bf16 (baseline PTX)
// ---------------------------------------------------------------------------
__device__ __forceinline__ void mma16816(float* c, const uint32_t* a, const uint32_t* b)
{
    asm volatile("mma.sync.aligned.m16n8k16.row.col.f32.bf16.bf16.f32 "
        "{%0,%1,%2,%3}, {%4,%5,%6,%7}, {%8,%9}, {%0,%1,%2,%3};"
        : "+f"(c[0]), "+f"(c[1]), "+f"(c[2]), "+f"(c[3])
        : "r"(a[0]), "r"(a[1]), "r"(a[2]), "r"(a[3]), "r"(b[0]), "r"(b[1]));
}

__device__ __forceinline__ uint32_t smem_u32(const void* p) {
    uint32_t a;
    asm("{ .reg .u64 t; cvta.to.shared.u64 t, %1; cvt.u32.u64 %0, t; }" : "=r"(a) : "l"(p));
    return a;
}

__device__ __forceinline__ uint32_t pack_bf16x2(float lo, float hi) {
    __nv_bfloat162 r = __floats2bfloat162_rn(lo, hi);
    return *(uint32_t*)&r;
}

// split helpers
__device__ __forceinline__ void split2(float v0, float v1, uint32_t& hi, uint32_t& lo) {
    __nv_bfloat16 h0 = __float2bfloat16_rn(v0), h1 = __float2bfloat16_rn(v1);
    __nv_bfloat16 l0 = __float2bfloat16_rn(v0 - __bfloat162float(h0));
    __nv_bfloat16 l1 = __float2bfloat16_rn(v1 - __bfloat162float(h1));
    __nv_bfloat162 h = __nv_bfloat162(h0, h1), l = __nv_bfloat162(l0, l1);
    hi = *(uint32_t*)&h; lo = *(uint32_t*)&l;
}

// ---------------------------------------------------------------------------
// Split kernels for the GEMM inputs
// ---------------------------------------------------------------------------
__global__ void split_plain(const float* __restrict__ in, __nv_bfloat16* __restrict__ hi,
                            __nv_bfloat16* __restrict__ lo, int n4)
{
    int i = blockIdx.x * blockDim.x + threadIdx.x;
    if (i >= n4) return;
    float4 a = ((const float4*)in)[i];
    uint32_t h0, l0, h1, l1;
    split2(a.x, a.y, h0, l0);
    split2(a.z, a.w, h1, l1);
    ((uint32_t*)hi)[2*i] = h0; ((uint32_t*)hi)[2*i+1] = h1;
    ((uint32_t*)lo)[2*i] = l0; ((uint32_t*)lo)[2*i+1] = l1;
}

__global__ void split_transpose(const float* __restrict__ in, __nv_bfloat16* __restrict__ hi,
                                __nv_bfloat16* __restrict__ lo)
{
    __shared__ float t[32][33];
    const int k0 = blockIdx.y * 32, n0 = blockIdx.x * 32;
    const int tx = threadIdx.x, ty = threadIdx.y;   // 32 x 8
#pragma unroll
    for (int i = 0; i < 32; i += 8)
        t[ty + i][tx] = in[(size_t)(k0 + ty + i) * D_ + n0 + tx];
    __syncthreads();
#pragma unroll
    for (int i = 0; i < 32; i += 8) {
        float a = t[tx][ty + i];
        __nv_bfloat16 h = __float2bfloat16_rn(a);
        __nv_bfloat16 l = __float2bfloat16_rn(a - __bfloat162float(h));
        hi[(size_t)(n0 + ty + i) * D_ + k0 + tx] = h;
        lo[(size_t)(n0 + ty + i) * D_ + k0 + tx] = l;
    }
}

// ---------------------------------------------------------------------------
// HMMA GEMM (as round 4) — epilogue variants:
// MODE 0: fp32 + bias -> Cout
// MODE 1/2/3: bias, then bf16 hi/lo split -> g_{q,k,v}{hi,lo} as [B,H,S,HD]
// ---------------------------------------------------------------------------
#define LDSG 40
#define NKIT 96   // 3 phases x (1024/32)

template<int MODE>
__global__ void __launch_bounds__(256, 2)
gemm_tc(const __nv_bfloat16* __restrict__ Ahi, const __nv_bfloat16* __restrict__ Alo,
        const __nv_bfloat16* __restrict__ Bhi, const __nv_bfloat16* __restrict__ Blo,
        const float* __restrict__ bias, float* __restrict__ Cout)
{
    __shared__ __nv_bfloat16 sA[2][128][LDSG];
    __shared__ __nv_bfloat16 sB[2][128][LDSG];

    const int tid  = threadIdx.x;
    const int wid  = tid >> 5, lane = tid & 31;
    const int g    = lane >> 2, t4 = lane & 3;
    const int wm   = (wid >> 2) * 64;
    const int wn   = (wid & 3) * 32;
    const int bM   = blockIdx.y * 128, bN = blockIdx.x * 128;

    const int rowL = tid >> 1;
    const int colL = (tid & 1) * 8;
    const size_t aRow = (size_t)(bM + rowL) * D_;
    const size_t bRow = (size_t)(bN + rowL) * D_;

    float acc[4][4][4];
#pragma unroll
    for (int mi = 0; mi < 4; mi++)
#pragma unroll
        for (int ni = 0; ni < 4; ni++)
#pragma unroll
            for (int r = 0; r < 4; r++) acc[mi][ni][r] = 0.f;

    auto srcA = [&](int kc) { return (kc < 64) ? Ahi : Alo; };
    auto srcB = [&](int kc) { return (kc >= 32 && kc < 64) ? Blo : Bhi; };
    auto koff = [&](int kc) { return (size_t)(kc & 31) * 32; };

    {
        const __nv_bfloat16* A = srcA(0);
        const __nv_bfloat16* Bp = srcB(0);
#pragma unroll
        for (int it = 0; it < 2; it++) {
            const int c = colL + it * 16;
            *(uint4*)&sA[0][rowL][c] = *(const uint4*)(A  + aRow + c);
            *(uint4*)&sB[0][rowL][c] = *(const uint4*)(Bp + bRow + c);
        }
    }
    __syncthreads();

    for (int kc = 0; kc < NKIT; kc++) {
        const int cur = kc & 1, nxt = cur ^ 1;
        uint4 ra[2], rb[2];
        const bool more = (kc + 1 < NKIT);
        if (more) {
            const __nv_bfloat16* A = srcA(kc + 1);
            const __nv_bfloat16* Bp = srcB(kc + 1);
            const size_t k0 = koff(kc + 1);
#pragma unroll
            for (int it = 0; it < 2; it++) {
                const int c = colL + it * 16;
                ra[it] = *(const uint4*)(A  + aRow + k0 + c);
                rb[it] = *(const uint4*)(Bp + bRow + k0 + c);
            }
        }

#pragma unroll
        for (int ks = 0; ks < 2; ks++) {
            const int k0 = ks * 16;
            uint32_t af[4][4];
#pragma unroll
            for (int mi = 0; mi < 4; mi++) {
                const int r0 = wm + mi * 16 + g;
                af[mi][0] = *(const uint32_t*)&sA[cur][r0    ][k0 + t4 * 2];
                af[mi][1] = *(const uint32_t*)&sA[cur][r0 + 8][k0 + t4 * 2];
                af[mi][2] = *(const uint32_t*)&sA[cur][r0    ][k0 + 8 + t4 * 2];
                af[mi][3] = *(const uint32_t*)&sA[cur][r0 + 8][k0 + 8 + t4 * 2];
            }
            uint32_t bf[4][2];
#pragma unroll
            for (int ni = 0; ni < 4; ni++) {
                const int n = wn + ni * 8 + g;
                bf[ni][0] = *(const uint32_t*)&sB[cur][n][k0 + t4 * 2];
                bf[ni][1] = *(const uint32_t*)&sB[cur][n][k0 + 8 + t4 * 2];
            }
#pragma unroll
            for (int mi = 0; mi < 4; mi++)
#pragma unroll
                for (int ni = 0; ni < 4; ni++)
                    mma16816(acc[mi][ni], af[mi], bf[ni]);
        }

        if (more) {
#pragma unroll
            for (int it = 0; it < 2; it++) {
                const int c = colL + it * 16;
                *(uint4*)&sA[nxt][rowL][c] = ra[it];
                *(uint4*)&sB[nxt][rowL][c] = rb[it];
            }
        }
        __syncthreads();
    }

#pragma unroll
    for (int mi = 0; mi < 4; mi++) {
#pragma unroll
        for (int hm = 0; hm < 2; hm++) {
            const int m = bM + wm + mi * 16 + g + hm * 8;
#pragma unroll
            for (int ni = 0; ni < 4; ni++) {
                const int n = bN + wn + ni * 8 + t4 * 2;
                const float v0 = acc[mi][ni][hm * 2 + 0] + bias[n];
                const float v1 = acc[mi][ni][hm * 2 + 1] + bias[n + 1];
                if (MODE == 0) {
                    *(float2*)(Cout + (size_t)m * D_ + n) = make_float2(v0, v1);
                } else {
                    __nv_bfloat16* Gh = (MODE == 1) ? g_qhi : (MODE == 2) ? g_khi : g_vhi;
                    __nv_bfloat16* Gl = (MODE == 1) ? g_qlo : (MODE == 2) ? g_klo : g_vlo;
                    const int bb = m >> 11, ss = m & (S_ - 1);
                    const int h = n >> 6, hd = n & 63;
                    const size_t o = (((size_t)(bb * H_ + h) * S_ + ss) << 6) + hd;
                    uint32_t hi, lo;
                    split2(v0, v1, hi, lo);
                    *(uint32_t*)(Gh + o) = hi;
                    *(uint32_t*)(Gl + o) = lo;
                }
            }
        }
    }
}

// ---------------------------------------------------------------------------
// Tensor-core flash attention.
// Block: 128 queries of one (b,h); 256 threads = 8 warps; warp tile 16q x 64k.
// Q frags in registers (hi/lo); K via conflict-free LDS.32; V via ldmatrix.trans.
// QK^T: qh*kh + qh*kl + ql*kh; softmax fp32 warp-local; PV: ph*vh + pl*vh + ph*vl.
// Emits bf16 hi/lo attention output to g_aohi/g_aolo ([B,S,D]).
// ---------------------------------------------------------------------------
#define PAD 72
#define ATT_SMEM (4 * 64 * PAD * 2)   // 36864 bytes

__global__ void __launch_bounds__(256, 1)
attn_tc()
{
    extern __shared__ __nv_bfloat16 sm[];
    const uint32_t smb = smem_u32(sm);

    const int tid  = threadIdx.x;
    const int wid  = tid >> 5, lane = tid & 31;
    const int g    = lane >> 2, t4 = lane & 3;
    const int q0   = blockIdx.x * 128;
    const int bh   = blockIdx.y;
    const int b    = bh >> 4, h = bh & 15;

    const size_t bhOff = (size_t)bh * (S_ * HD_);
    const __nv_bfloat16* Qh = g_qhi + bhOff + (size_t)q0 * HD_;
    const __nv_bfloat16* Ql = g_qlo + bhOff + (size_t)q0 * HD_;
    const __nv_bfloat16* Kh = g_khi + bhOff;
    const __nv_bfloat16* Kl = g_klo + bhOff;
    const __nv_bfloat16* Vh = g_vhi + bhOff;
    const __nv_bfloat16* Vl = g_vlo + bhOff;

    // ---- stage Q into smem, pull frags into registers ----
    // layout: Qhi at 0, Qlo at 128*PAD
#pragma unroll
    for (int i = 0; i < 4; i++) {
        const int idx = tid + i * 256;          // 0..1023
        const int row = idx >> 3, c8 = (idx & 7) * 8;
        *(uint4*)&sm[row * PAD + c8]             = *(const uint4*)(Qh + row * HD_ + c8);
        *(uint4*)&sm[128 * PAD + row * PAD + c8] = *(const uint4*)(Ql + row * HD_ + c8);
    }
    __syncthreads();

    uint32_t qh[4][4], ql[4][4];
    {
        const int qr = wid * 16 + g;
#pragma unroll
        for (int kc = 0; kc < 4; kc++) {
            const int base = qr * PAD + kc * 16 + t4 * 2;
            qh[kc][0] = *(const uint32_t*)&sm[base];
            qh[kc][1] = *(const uint32_t*)&sm[base + 8 * PAD];
            qh[kc][2] = *(const uint32_t*)&sm[base + 8];
            qh[kc][3] = *(const uint32_t*)&sm[base + 8 * PAD + 8];
            ql[kc][0] = *(const uint32_t*)&sm[128 * PAD + base];
            ql[kc][1] = *(const uint32_t*)&sm[128 * PAD + base + 8 * PAD];
            ql[kc][2] = *(const uint32_t*)&sm[128 * PAD + base + 8];
            ql[kc][3] = *(const uint32_t*)&sm[128 * PAD + base + 8 * PAD + 8];
        }
    }
    __syncthreads();   // Q region will be reused for K/V

    // K/V smem layout (bf16 indices)
    const int KHI = 0, KLO = 64 * PAD, VHI = 2 * 64 * PAD, VLO = 3 * 64 * PAD;

    float o[8][4];
#pragma unroll
    for (int j = 0; j < 8; j++)
#pragma unroll
        for (int r = 0; r < 4; r++) o[j][r] = 0.f;
    float m0 = -1e30f, m1 = -1e30f, l0 = 0.f, l1 = 0.f;

    for (int kt = 0; kt < S_ / 64; kt++) {
        // ---- load K/V tile (hi+lo) ----
#pragma unroll
        for (int i = 0; i < 2; i++) {
            const int idx = tid + i * 256;      // 0..511
            const int row = idx >> 3, c8 = (idx & 7) * 8;
            const size_t gidx = (size_t)(kt * 64 + row) * HD_ + c8;
            const int so = row * PAD + c8;
            *(uint4*)&sm[KHI + so] = *(const uint4*)(Kh + gidx);
            *(uint4*)&sm[KLO + so] = *(const uint4*)(Kl + gidx);
            *(uint4*)&sm[VHI + so] = *(const uint4*)(Vh + gidx);
            *(uint4*)&sm[VLO + so] = *(const uint4*)(Vl + gidx);
        }
        __syncthreads();

        // ---- S = Q K^T (3-pass split) ----
        float c[8][4];
#pragma unroll
        for (int j = 0; j < 8; j++)
#pragma unroll
            for (int r = 0; r < 4; r++) c[j][r] = 0.f;

#pragma unroll
        for (int kc = 0; kc < 4; kc++) {
#pragma unroll
            for (int nt = 0; nt < 8; nt++) {
                const int kb = (nt * 8 + g) * PAD + kc * 16 + t4 * 2;
                uint32_t bh2[2], bl2[2];
                bh2[0] = *(const uint32_t*)&sm[KHI + kb];
                bh2[1] = *(const uint32_t*)&sm[KHI + kb + 8];
                bl2[0] = *(const uint32_t*)&sm[KLO + kb];
                bl2[1] = *(const uint32_t*)&sm[KLO + kb + 8];
                mma16816(c[nt], qh[kc], bh2);
                mma16816(c[nt], qh[kc], bl2);
                mma16816(c[nt], ql[kc], bh2);
            }
        }

        // ---- online softmax (rows g and g+8, warp-local) ----
        const float sc = 0.125f;
        float mx0 = -1e30f, mx1 = -1e30f;
#pragma unroll
        for (int j = 0; j < 8; j++) {
            c[j][0] *= sc; c[j][1] *= sc; c[j][2] *= sc; c[j][3] *= sc;
            mx0 = fmaxf(mx0, fmaxf(c[j][0], c[j][1]));
            mx1 = fmaxf(mx1, fmaxf(c[j][2], c[j][3]));
        }
#pragma unroll
        for (int off = 1; off <= 2; off <<= 1) {
            mx0 = fmaxf(mx0, __shfl_xor_sync(0xffffffffu, mx0, off));
            mx1 = fmaxf(mx1, __shfl_xor_sync(0xffffffffu, mx1, off));
        }
        const float nm0 = fmaxf(m0, mx0), nm1 = fmaxf(m1, mx1);
        const float cr0 = __expf(m0 - nm0), cr1 = __expf(m1 - nm1);
        float rs0 = 0.f, rs1 = 0.f;
#pragma unroll
        for (int j = 0; j < 8; j++) {
            c[j][0] = __expf(c[j][0] - nm0);
            c[j][1] = __expf(c[j][1] - nm0);
            c[j][2] = __expf(c[j][2] - nm1);
            c[j][3] = __expf(c[j][3] - nm1);
            rs0 += c[j][0] + c[j][1];
            rs1 += c[j][2] + c[j][3];
        }
#pragma unroll
        for (int off = 1; off <= 2; off <<= 1) {
            rs0 += __shfl_xor_sync(0xffffffffu, rs0, off);
            rs1 += __shfl_xor_sync(0xffffffffu, rs1, off);
        }
        l0 = l0 * cr0 + rs0;  m0 = nm0;
        l1 = l1 * cr1 + rs1;  m1 = nm1;
#pragma unroll
        for (int j = 0; j < 8; j++) {
            o[j][0] *= cr0; o[j][1] *= cr0;
            o[j][2] *= cr1; o[j][3] *= cr1;
        }

        // ---- O += P V (3-pass split; P split in-register) ----
#pragma unroll
        for (int kc = 0; kc < 4; kc++) {
            uint32_t ah[4], al[4];
            split2(c[2*kc  ][0], c[2*kc  ][1], ah[0], al[0]);
            split2(c[2*kc  ][2], c[2*kc  ][3], ah[1], al[1]);
            split2(c[2*kc+1][0], c[2*kc+1][1], ah[2], al[2]);
            split2(c[2*kc+1][2], c[2*kc+1][3], ah[3], al[3]);

            // lane-specific ldmatrix row address pieces
            const int r = lane >> 3, i = lane & 7;
            const int vrow = kc * 16 + (r & 1) * 8 + i;
            const int vcolp = (r >> 1) * 8;

            uint32_t vb[4][4];
#pragma unroll
            for (int np = 0; np < 4; np++) {
                const uint32_t addr = smb + 2u * (uint32_t)(VHI + vrow * PAD + np * 16 + vcolp);
                asm volatile("ldmatrix.sync.aligned.m8n8.x4.trans.shared.b16 {%0,%1,%2,%3}, [%4];"
                    : "=r"(vb[np][0]), "=r"(vb[np][1]), "=r"(vb[np][2]), "=r"(vb[np][3])
                    : "r"(addr));
            }
#pragma unroll
            for (int nt = 0; nt < 8; nt++) {
                uint32_t bb[2] = { vb[nt >> 1][(nt & 1) * 2], vb[nt >> 1][(nt & 1) * 2 + 1] };
                mma16816(o[nt], ah, bb);
                mma16816(o[nt], al, bb);
            }
#pragma unroll
            for (int np = 0; np < 4; np++) {
                const uint32_t addr = smb + 2u * (uint32_t)(VLO + vrow * PAD + np * 16 + vcolp);
                asm volatile("ldmatrix.sync.aligned.m8n8.x4.trans.shared.b16 {%0,%1,%2,%3}, [%4];"
                    : "=r"(vb[np][0]), "=r"(vb[np][1]), "=r"(vb[np][2]), "=r"(vb[np][3])
                    : "r"(addr));
            }
#pragma unroll
            for (int nt = 0; nt < 8; nt++) {
                uint32_t bb[2] = { vb[nt >> 1][(nt & 1) * 2], vb[nt >> 1][(nt & 1) * 2 + 1] };
                mma16816(o[nt], ah, bb);
            }
        }
        __syncthreads();
    }

    // ---- epilogue: normalize, split, write [B,S,D] bf16 hi/lo ----
    const float inv0 = 1.f / l0, inv1 = 1.f / l1;
    const int row0 = q0 + wid * 16 + g;
#pragma unroll
    for (int j = 0; j < 8; j++) {
        const int d = h * HD_ + j * 8 + t4 * 2;
        uint32_t hi, lo;
        split2(o[j][0] * inv0, o[j][1] * inv0, hi, lo);
        const size_t o0 = (size_t)(b * S_ + row0) * D_ + d;
        *(uint32_t*)(g_aohi + o0) = hi;
        *(uint32_t*)(g_aolo + o0) = lo;
        split2(o[j][2] * inv1, o[j][3] * inv1, hi, lo);
        const size_t o1 = (size_t)(b * S_ + row0 + 8) * D_ + d;
        *(uint32_t*)(g_aohi + o1) = hi;
        *(uint32_t*)(g_aolo + o1) = lo;
    }
}

// ---------------------------------------------------------------------------

extern "C" void kernel_launch(void* const* d_in, const int* in_sizes, int n_in,
                              void* d_out, int out_size)
{
    const float* x  = (const float*)d_in[0];
    const float* Wq = (const float*)d_in[1];
    const float* bq = (const float*)d_in[2];
    const float* Wk = (const float*)d_in[3];
    const float* bk = (const float*)d_in[4];
    const float* Wv = (const float*)d_in[5];
    const float* bv = (const float*)d_in[6];
    const float* Wo = (const float*)d_in[7];
    const float* bo = (const float*)d_in[8];
    float* out = (float*)d_out;

    void *p_xhi, *p_xlo, *p_aohi, *p_aolo, *p_whi, *p_wlo;
    cudaGetSymbolAddress(&p_xhi,  g_xhi);
    cudaGetSymbolAddress(&p_xlo,  g_xlo);
    cudaGetSymbolAddress(&p_aohi, g_aohi);
    cudaGetSymbolAddress(&p_aolo, g_aolo);
    cudaGetSymbolAddress(&p_whi,  g_whi);
    cudaGetSymbolAddress(&p_wlo,  g_wlo);
    __nv_bfloat16* xhi  = (__nv_bfloat16*)p_xhi;
    __nv_bfloat16* xlo  = (__nv_bfloat16*)p_xlo;
    __nv_bfloat16* aohi = (__nv_bfloat16*)p_aohi;
    __nv_bfloat16* aolo = (__nv_bfloat16*)p_aolo;
    __nv_bfloat16* whi  = (__nv_bfloat16*)p_whi;
    __nv_bfloat16* wlo  = (__nv_bfloat16*)p_wlo;

    const int n4 = M_ * D_ / 4;
    dim3 tb(32, 8), tg(D_/32, D_/32);

    split_plain<<<(n4 + 255)/256, 256>>>(x, xhi, xlo, n4);
    split_transpose<<<tg, tb>>>(Wq, whi + 0*(size_t)D_*D_, wlo + 0*(size_t)D_*D_);
    split_transpose<<<tg, tb>>>(Wk, whi + 1*(size_t)D_*D_, wlo + 1*(size_t)D_*D_);
    split_transpose<<<tg, tb>>>(Wv, whi + 2*(size_t)D_*D_, wlo + 2*(size_t)D_*D_);
    split_transpose<<<tg, tb>>>(Wo, whi + 3*(size_t)D_*D_, wlo + 3*(size_t)D_*D_);

    dim3 gg(D_/128, M_/128);
    gemm_tc<1><<<gg, 256>>>(xhi, xlo, whi + 0*(size_t)D_*D_, wlo + 0*(size_t)D_*D_, bq, nullptr);
    gemm_tc<2><<<gg, 256>>>(xhi, xlo, whi + 1*(size_t)D_*D_, wlo + 1*(size_t)D_*D_, bk, nullptr);
    gemm_tc<3><<<gg, 256>>>(xhi, xlo, whi + 2*(size_t)D_*D_, wlo + 2*(size_t)D_*D_, bv, nullptr);

    attn_tc<<<dim3(S_/128, B_*H_), 256, ATT_SMEM>>>();

    gemm_tc<0><<<gg, 256>>>(aohi, aolo, whi + 3*(size_t)D_*D_, wlo + 3*(size_t)D_*D_, bo, out);
}

// round 6
// speedup vs baseline: 2.7599x; 1.2564x over previous
#include <cuda_runtime.h>
#include <cuda_bf16.h>
#include <stdint.h>
#include <math.h>

#define B_  2
#define S_  2048
#define D_  1024
#define H_  16
#define HD_ 64
#define M_  (B_*S_)        // 4096 rows

// ---------------------------------------------------------------------------
// Scratch (__device__ globals; no allocs allowed)
// ---------------------------------------------------------------------------
__device__ __nv_bfloat16 g_qhi[B_*H_*S_*HD_], g_qlo[B_*H_*S_*HD_];   // [B,H,S,HD]
__device__ __nv_bfloat16 g_khi[B_*H_*S_*HD_], g_klo[B_*H_*S_*HD_];
__device__ __nv_bfloat16 g_vhi[B_*H_*S_*HD_], g_vlo[B_*H_*S_*HD_];
__device__ __nv_bfloat16 g_aohi[M_*D_], g_aolo[M_*D_];               // [B,S,D]
__device__ __nv_bfloat16 g_xhi[M_*D_],  g_xlo[M_*D_];                // x split
__device__ __nv_bfloat16 g_whi[4][D_*D_], g_wlo[4][D_*D_];           // W^T splits

// ---------------------------------------------------------------------------
// PTX primitives (all baseline, valid on compute_103)
// ---------------------------------------------------------------------------
__device__ __forceinline__ void mma16816(float* c, const uint32_t* a, const uint32_t* b)
{
    asm volatile("mma.sync.aligned.m16n8k16.row.col.f32.bf16.bf16.f32 "
        "{%0,%1,%2,%3}, {%4,%5,%6,%7}, {%8,%9}, {%0,%1,%2,%3};"
        : "+f"(c[0]), "+f"(c[1]), "+f"(c[2]), "+f"(c[3])
        : "r"(a[0]), "r"(a[1]), "r"(a[2]), "r"(a[3]), "r"(b[0]), "r"(b[1]));
}

__device__ __forceinline__ uint32_t smem_u32(const void* p) {
    uint32_t a;
    asm("{ .reg .u64 t; cvta.to.shared.u64 t, %1; cvt.u32.u64 %0, t; }" : "=r"(a) : "l"(p));
    return a;
}

__device__ __forceinline__ void ldm_x4(uint32_t& r0, uint32_t& r1, uint32_t& r2,
                                       uint32_t& r3, uint32_t addr) {
    asm volatile("ldmatrix.sync.aligned.m8n8.x4.shared.b16 {%0,%1,%2,%3}, [%4];"
        : "=r"(r0), "=r"(r1), "=r"(r2), "=r"(r3) : "r"(addr));
}

__device__ __forceinline__ void cp16(uint32_t s, const void* g) {
    asm volatile("cp.async.cg.shared.global [%0], [%1], 16;" :: "r"(s), "l"(g));
}
#define CP_COMMIT() asm volatile("cp.async.commit_group;" ::: "memory")
#define CP_WAIT1()  asm volatile("cp.async.wait_group 1;" ::: "memory")

// split helpers
__device__ __forceinline__ void split2(float v0, float v1, uint32_t& hi, uint32_t& lo) {
    __nv_bfloat16 h0 = __float2bfloat16_rn(v0), h1 = __float2bfloat16_rn(v1);
    __nv_bfloat16 l0 = __float2bfloat16_rn(v0 - __bfloat162float(h0));
    __nv_bfloat16 l1 = __float2bfloat16_rn(v1 - __bfloat162float(h1));
    __nv_bfloat162 h = __nv_bfloat162(h0, h1), l = __nv_bfloat162(l0, l1);
    hi = *(uint32_t*)&h; lo = *(uint32_t*)&l;
}

// ---------------------------------------------------------------------------
// Split kernels for the GEMM inputs
// ---------------------------------------------------------------------------
__global__ void split_plain(const float* __restrict__ in, __nv_bfloat16* __restrict__ hi,
                            __nv_bfloat16* __restrict__ lo, int n4)
{
    int i = blockIdx.x * blockDim.x + threadIdx.x;
    if (i >= n4) return;
    float4 a = ((const float4*)in)[i];
    uint32_t h0, l0, h1, l1;
    split2(a.x, a.y, h0, l0);
    split2(a.z, a.w, h1, l1);
    ((uint32_t*)hi)[2*i] = h0; ((uint32_t*)hi)[2*i+1] = h1;
    ((uint32_t*)lo)[2*i] = l0; ((uint32_t*)lo)[2*i+1] = l1;
}

__global__ void split_transpose(const float* __restrict__ in, __nv_bfloat16* __restrict__ hi,
                                __nv_bfloat16* __restrict__ lo)
{
    __shared__ float t[32][33];
    const int k0 = blockIdx.y * 32, n0 = blockIdx.x * 32;
    const int tx = threadIdx.x, ty = threadIdx.y;   // 32 x 8
#pragma unroll
    for (int i = 0; i < 32; i += 8)
        t[ty + i][tx] = in[(size_t)(k0 + ty + i) * D_ + n0 + tx];
    __syncthreads();
#pragma unroll
    for (int i = 0; i < 32; i += 8) {
        float a = t[tx][ty + i];
        __nv_bfloat16 h = __float2bfloat16_rn(a);
        __nv_bfloat16 l = __float2bfloat16_rn(a - __bfloat162float(h));
        hi[(size_t)(n0 + ty + i) * D_ + k0 + tx] = h;
        lo[(size_t)(n0 + ty + i) * D_ + k0 + tx] = l;
    }
}

// ---------------------------------------------------------------------------
// HMMA GEMM, cp.async 3-stage + ldmatrix frags. C = A[M,K] x B[N,K]^T (split).
// MODE 0: fp32 + bias(b0) -> Cout.
// MODE 4: fused QKV (N=3072): which = bN>>10 picks bias b0/b1/b2 and the
//         q/k/v hi-lo destination ([B,H,S,HD] scatter with bf16 re-split).
// ---------------------------------------------------------------------------
#define LDSG   40
#define GSTAGE (128 * LDSG)                // elems per matrix per stage
#define GSMEM  (3 * 2 * GSTAGE * 2)        // bytes (3 stages x A,B x bf16)
#define NKIT   96                          // 3 phases x (1024/32)

template<int MODE>
__global__ void __launch_bounds__(256, 2)
gemm_tc(const __nv_bfloat16* __restrict__ Ahi, const __nv_bfloat16* __restrict__ Alo,
        const __nv_bfloat16* __restrict__ Bhi, const __nv_bfloat16* __restrict__ Blo,
        const float* __restrict__ b0, const float* __restrict__ b1,
        const float* __restrict__ b2, float* __restrict__ Cout)
{
    extern __shared__ __nv_bfloat16 sg[];
    const uint32_t smb = smem_u32(sg);

    const int tid  = threadIdx.x;
    const int wid  = tid >> 5, lane = tid & 31;
    const int g    = lane >> 2, t4 = lane & 3;
    const int r8   = lane & 7,  grp = lane >> 3;
    const int wm   = (wid >> 2) * 64;
    const int wn   = (wid & 3) * 32;
    const int bM   = blockIdx.y * 128, bN = blockIdx.x * 128;

    const int rowL = tid >> 1;
    const int colL = (tid & 1) * 16;       // 0 or 16 (two 16B chunks each)
    const size_t aRow = (size_t)(bM + rowL) * D_;
    const size_t bRow = (size_t)(bN + rowL) * D_;

    auto srcA = [&](int kc) { return (kc < 64) ? Ahi : Alo; };
    auto srcB = [&](int kc) { return (kc >= 32 && kc < 64) ? Blo : Bhi; };
    auto koff = [&](int kc) { return (size_t)(kc & 31) * 32; };

    const uint32_t sAld = smb + 2u * (rowL * LDSG + colL);
    const uint32_t sBld = smb + 2u * (3 * GSTAGE + rowL * LDSG + colL);

    auto issue = [&](int kc) {
        const int st = kc % 3;
        const __nv_bfloat16* A  = srcA(kc);
        const __nv_bfloat16* Bp = srcB(kc);
        const size_t k0 = koff(kc);
        const uint32_t sa = sAld + 2u * st * GSTAGE;
        const uint32_t sb = sBld + 2u * st * GSTAGE;
        cp16(sa,      A  + aRow + k0 + colL);
        cp16(sa + 16, A  + aRow + k0 + colL + 8);
        cp16(sb,      Bp + bRow + k0 + colL);
        cp16(sb + 16, Bp + bRow + k0 + colL + 8);
        CP_COMMIT();
    };

    float acc[4][4][4];
#pragma unroll
    for (int mi = 0; mi < 4; mi++)
#pragma unroll
        for (int ni = 0; ni < 4; ni++)
#pragma unroll
            for (int r = 0; r < 4; r++) acc[mi][ni][r] = 0.f;

    issue(0);
    issue(1);

    for (int kc = 0; kc < NKIT; kc++) {
        const int st = kc % 3;
        CP_WAIT1();
        __syncthreads();
        const uint32_t sAb = smb + 2u * (st * GSTAGE);
        const uint32_t sBb = smb + 2u * (3 * GSTAGE + st * GSTAGE);

#pragma unroll
        for (int ks = 0; ks < 2; ks++) {
            const int k0 = ks * 16;
            uint32_t af[4][4];
#pragma unroll
            for (int mi = 0; mi < 4; mi++) {
                const int row = wm + mi * 16 + r8 + (grp & 1) * 8;
                const int col = k0 + (grp >> 1) * 8;
                ldm_x4(af[mi][0], af[mi][1], af[mi][2], af[mi][3],
                       sAb + 2u * (row * LDSG + col));
            }
            uint32_t bf[4][2];
#pragma unroll
            for (int p = 0; p < 2; p++) {
                const int row = wn + p * 16 + r8 + (grp >> 1) * 8;
                const int col = k0 + (grp & 1) * 8;
                ldm_x4(bf[2*p][0], bf[2*p][1], bf[2*p+1][0], bf[2*p+1][1],
                       sBb + 2u * (row * LDSG + col));
            }
#pragma unroll
            for (int mi = 0; mi < 4; mi++)
#pragma unroll
                for (int ni = 0; ni < 4; ni++)
                    mma16816(acc[mi][ni], af[mi], bf[ni]);
        }
        if (kc + 2 < NKIT) issue(kc + 2);
    }

    // ---- epilogue ----
    const float* bias;
    __nv_bfloat16 *Gh = nullptr, *Gl = nullptr;
    int nBase = bN;
    if (MODE == 4) {
        const int which = bN >> 10;
        bias = (which == 0) ? b0 : (which == 1) ? b1 : b2;
        Gh = (which == 0) ? g_qhi : (which == 1) ? g_khi : g_vhi;
        Gl = (which == 0) ? g_qlo : (which == 1) ? g_klo : g_vlo;
        nBase = bN & 1023;
    } else {
        bias = b0;
    }

#pragma unroll
    for (int mi = 0; mi < 4; mi++) {
#pragma unroll
        for (int hm = 0; hm < 2; hm++) {
            const int m = bM + wm + mi * 16 + g + hm * 8;
#pragma unroll
            for (int ni = 0; ni < 4; ni++) {
                const int nl = nBase + wn + ni * 8 + t4 * 2;
                const float v0 = acc[mi][ni][hm * 2 + 0] + bias[nl];
                const float v1 = acc[mi][ni][hm * 2 + 1] + bias[nl + 1];
                if (MODE == 0) {
                    *(float2*)(Cout + (size_t)m * D_ + nl) = make_float2(v0, v1);
                } else {
                    const int bb = m >> 11, ss = m & (S_ - 1);
                    const int h = nl >> 6, hd = nl & 63;
                    const size_t o = (((size_t)(bb * H_ + h) * S_ + ss) << 6) + hd;
                    uint32_t hi, lo;
                    split2(v0, v1, hi, lo);
                    *(uint32_t*)(Gh + o) = hi;
                    *(uint32_t*)(Gl + o) = lo;
                }
            }
        }
    }
}

// ---------------------------------------------------------------------------
// Tensor-core flash attention (as r5) with ldmatrix K-fragment loads.
// ---------------------------------------------------------------------------
#define PAD 72
#define ATT_SMEM (4 * 64 * PAD * 2)   // 36864 bytes

__global__ void __launch_bounds__(256, 1)
attn_tc()
{
    extern __shared__ __nv_bfloat16 sm[];
    const uint32_t smb = smem_u32(sm);

    const int tid  = threadIdx.x;
    const int wid  = tid >> 5, lane = tid & 31;
    const int g    = lane >> 2, t4 = lane & 3;
    const int r8   = lane & 7,  grp = lane >> 3;
    const int q0   = blockIdx.x * 128;
    const int bh   = blockIdx.y;
    const int b    = bh >> 4, h = bh & 15;

    const size_t bhOff = (size_t)bh * (S_ * HD_);
    const __nv_bfloat16* Qh = g_qhi + bhOff + (size_t)q0 * HD_;
    const __nv_bfloat16* Ql = g_qlo + bhOff + (size_t)q0 * HD_;
    const __nv_bfloat16* Kh = g_khi + bhOff;
    const __nv_bfloat16* Kl = g_klo + bhOff;
    const __nv_bfloat16* Vh = g_vhi + bhOff;
    const __nv_bfloat16* Vl = g_vlo + bhOff;

    // ---- stage Q, pull frags to registers ----
#pragma unroll
    for (int i = 0; i < 4; i++) {
        const int idx = tid + i * 256;
        const int row = idx >> 3, c8 = (idx & 7) * 8;
        *(uint4*)&sm[row * PAD + c8]             = *(const uint4*)(Qh + row * HD_ + c8);
        *(uint4*)&sm[128 * PAD + row * PAD + c8] = *(const uint4*)(Ql + row * HD_ + c8);
    }
    __syncthreads();

    uint32_t qh[4][4], ql[4][4];
    {
#pragma unroll
        for (int kc = 0; kc < 4; kc++) {
            const int row = wid * 16 + r8 + (grp & 1) * 8;
            const int col = kc * 16 + (grp >> 1) * 8;
            ldm_x4(qh[kc][0], qh[kc][1], qh[kc][2], qh[kc][3],
                   smb + 2u * (row * PAD + col));
            ldm_x4(ql[kc][0], ql[kc][1], ql[kc][2], ql[kc][3],
                   smb + 2u * (128 * PAD + row * PAD + col));
        }
    }
    __syncthreads();

    const int KHI = 0, KLO = 64 * PAD, VHI = 2 * 64 * PAD, VLO = 3 * 64 * PAD;

    float o[8][4];
#pragma unroll
    for (int j = 0; j < 8; j++)
#pragma unroll
        for (int r = 0; r < 4; r++) o[j][r] = 0.f;
    float m0 = -1e30f, m1 = -1e30f, l0 = 0.f, l1 = 0.f;

    for (int kt = 0; kt < S_ / 64; kt++) {
#pragma unroll
        for (int i = 0; i < 2; i++) {
            const int idx = tid + i * 256;
            const int row = idx >> 3, c8 = (idx & 7) * 8;
            const size_t gidx = (size_t)(kt * 64 + row) * HD_ + c8;
            const int so = row * PAD + c8;
            *(uint4*)&sm[KHI + so] = *(const uint4*)(Kh + gidx);
            *(uint4*)&sm[KLO + so] = *(const uint4*)(Kl + gidx);
            *(uint4*)&sm[VHI + so] = *(const uint4*)(Vh + gidx);
            *(uint4*)&sm[VLO + so] = *(const uint4*)(Vl + gidx);
        }
        __syncthreads();

        // ---- S = Q K^T (3-pass, K frags via ldmatrix) ----
        float c[8][4];
#pragma unroll
        for (int j = 0; j < 8; j++)
#pragma unroll
            for (int r = 0; r < 4; r++) c[j][r] = 0.f;

#pragma unroll
        for (int kc = 0; kc < 4; kc++) {
#pragma unroll
            for (int p = 0; p < 4; p++) {
                const int row = p * 16 + r8 + (grp >> 1) * 8;
                const int col = kc * 16 + (grp & 1) * 8;
                uint32_t bhA[2], bhB[2], blA[2], blB[2];
                ldm_x4(bhA[0], bhA[1], bhB[0], bhB[1],
                       smb + 2u * (KHI + row * PAD + col));
                ldm_x4(blA[0], blA[1], blB[0], blB[1],
                       smb + 2u * (KLO + row * PAD + col));
                mma16816(c[2*p],   qh[kc], bhA);
                mma16816(c[2*p],   qh[kc], blA);
                mma16816(c[2*p],   ql[kc], bhA);
                mma16816(c[2*p+1], qh[kc], bhB);
                mma16816(c[2*p+1], qh[kc], blB);
                mma16816(c[2*p+1], ql[kc], bhB);
            }
        }

        // ---- online softmax (rows g and g+8, warp-local quads) ----
        const float sc = 0.125f;
        float mx0 = -1e30f, mx1 = -1e30f;
#pragma unroll
        for (int j = 0; j < 8; j++) {
            c[j][0] *= sc; c[j][1] *= sc; c[j][2] *= sc; c[j][3] *= sc;
            mx0 = fmaxf(mx0, fmaxf(c[j][0], c[j][1]));
            mx1 = fmaxf(mx1, fmaxf(c[j][2], c[j][3]));
        }
#pragma unroll
        for (int off = 1; off <= 2; off <<= 1) {
            mx0 = fmaxf(mx0, __shfl_xor_sync(0xffffffffu, mx0, off));
            mx1 = fmaxf(mx1, __shfl_xor_sync(0xffffffffu, mx1, off));
        }
        const float nm0 = fmaxf(m0, mx0), nm1 = fmaxf(m1, mx1);
        const float cr0 = __expf(m0 - nm0), cr1 = __expf(m1 - nm1);
        float rs0 = 0.f, rs1 = 0.f;
#pragma unroll
        for (int j = 0; j < 8; j++) {
            c[j][0] = __expf(c[j][0] - nm0);
            c[j][1] = __expf(c[j][1] - nm0);
            c[j][2] = __expf(c[j][2] - nm1);
            c[j][3] = __expf(c[j][3] - nm1);
            rs0 += c[j][0] + c[j][1];
            rs1 += c[j][2] + c[j][3];
        }
#pragma unroll
        for (int off = 1; off <= 2; off <<= 1) {
            rs0 += __shfl_xor_sync(0xffffffffu, rs0, off);
            rs1 += __shfl_xor_sync(0xffffffffu, rs1, off);
        }
        l0 = l0 * cr0 + rs0;  m0 = nm0;
        l1 = l1 * cr1 + rs1;  m1 = nm1;
#pragma unroll
        for (int j = 0; j < 8; j++) {
            o[j][0] *= cr0; o[j][1] *= cr0;
            o[j][2] *= cr1; o[j][3] *= cr1;
        }

        // ---- O += P V (3-pass; P split in-register; V via ldmatrix.trans) ----
#pragma unroll
        for (int kc = 0; kc < 4; kc++) {
            uint32_t ah[4], al[4];
            split2(c[2*kc  ][0], c[2*kc  ][1], ah[0], al[0]);
            split2(c[2*kc  ][2], c[2*kc  ][3], ah[1], al[1]);
            split2(c[2*kc+1][0], c[2*kc+1][1], ah[2], al[2]);
            split2(c[2*kc+1][2], c[2*kc+1][3], ah[3], al[3]);

            const int r = lane >> 3, i = lane & 7;
            const int vrow = kc * 16 + (r & 1) * 8 + i;
            const int vcolp = (r >> 1) * 8;

            uint32_t vb[4][4];
#pragma unroll
            for (int np = 0; np < 4; np++) {
                const uint32_t addr = smb + 2u * (uint32_t)(VHI + vrow * PAD + np * 16 + vcolp);
                asm volatile("ldmatrix.sync.aligned.m8n8.x4.trans.shared.b16 {%0,%1,%2,%3}, [%4];"
                    : "=r"(vb[np][0]), "=r"(vb[np][1]), "=r"(vb[np][2]), "=r"(vb[np][3])
                    : "r"(addr));
            }
#pragma unroll
            for (int nt = 0; nt < 8; nt++) {
                uint32_t bb[2] = { vb[nt >> 1][(nt & 1) * 2], vb[nt >> 1][(nt & 1) * 2 + 1] };
                mma16816(o[nt], ah, bb);
                mma16816(o[nt], al, bb);
            }
#pragma unroll
            for (int np = 0; np < 4; np++) {
                const uint32_t addr = smb + 2u * (uint32_t)(VLO + vrow * PAD + np * 16 + vcolp);
                asm volatile("ldmatrix.sync.aligned.m8n8.x4.trans.shared.b16 {%0,%1,%2,%3}, [%4];"
                    : "=r"(vb[np][0]), "=r"(vb[np][1]), "=r"(vb[np][2]), "=r"(vb[np][3])
                    : "r"(addr));
            }
#pragma unroll
            for (int nt = 0; nt < 8; nt++) {
                uint32_t bb[2] = { vb[nt >> 1][(nt & 1) * 2], vb[nt >> 1][(nt & 1) * 2 + 1] };
                mma16816(o[nt], ah, bb);
            }
        }
        __syncthreads();
    }

    // ---- epilogue: normalize, split, write [B,S,D] bf16 hi/lo ----
    const float inv0 = 1.f / l0, inv1 = 1.f / l1;
    const int row0 = q0 + wid * 16 + g;
#pragma unroll
    for (int j = 0; j < 8; j++) {
        const int d = h * HD_ + j * 8 + t4 * 2;
        uint32_t hi, lo;
        split2(o[j][0] * inv0, o[j][1] * inv0, hi, lo);
        const size_t o0 = (size_t)(b * S_ + row0) * D_ + d;
        *(uint32_t*)(g_aohi + o0) = hi;
        *(uint32_t*)(g_aolo + o0) = lo;
        split2(o[j][2] * inv1, o[j][3] * inv1, hi, lo);
        const size_t o1 = (size_t)(b * S_ + row0 + 8) * D_ + d;
        *(uint32_t*)(g_aohi + o1) = hi;
        *(uint32_t*)(g_aolo + o1) = lo;
    }
}

// ---------------------------------------------------------------------------

extern "C" void kernel_launch(void* const* d_in, const int* in_sizes, int n_in,
                              void* d_out, int out_size)
{
    const float* x  = (const float*)d_in[0];
    const float* Wq = (const float*)d_in[1];
    const float* bq = (const float*)d_in[2];
    const float* Wk = (const float*)d_in[3];
    const float* bk = (const float*)d_in[4];
    const float* Wv = (const float*)d_in[5];
    const float* bv = (const float*)d_in[6];
    const float* Wo = (const float*)d_in[7];
    const float* bo = (const float*)d_in[8];
    float* out = (float*)d_out;

    void *p_xhi, *p_xlo, *p_aohi, *p_aolo, *p_whi, *p_wlo;
    cudaGetSymbolAddress(&p_xhi,  g_xhi);
    cudaGetSymbolAddress(&p_xlo,  g_xlo);
    cudaGetSymbolAddress(&p_aohi, g_aohi);
    cudaGetSymbolAddress(&p_aolo, g_aolo);
    cudaGetSymbolAddress(&p_whi,  g_whi);
    cudaGetSymbolAddress(&p_wlo,  g_wlo);
    __nv_bfloat16* xhi  = (__nv_bfloat16*)p_xhi;
    __nv_bfloat16* xlo  = (__nv_bfloat16*)p_xlo;
    __nv_bfloat16* aohi = (__nv_bfloat16*)p_aohi;
    __nv_bfloat16* aolo = (__nv_bfloat16*)p_aolo;
    __nv_bfloat16* whi  = (__nv_bfloat16*)p_whi;
    __nv_bfloat16* wlo  = (__nv_bfloat16*)p_wlo;

    cudaFuncSetAttribute(attn_tc,
                         cudaFuncAttributeMaxDynamicSharedMemorySize, ATT_SMEM);
    cudaFuncSetAttribute(gemm_tc<0>, cudaFuncAttributeMaxDynamicSharedMemorySize, GSMEM);
    cudaFuncSetAttribute(gemm_tc<4>, cudaFuncAttributeMaxDynamicSharedMemorySize, GSMEM);

    const int n4 = M_ * D_ / 4;
    dim3 tb(32, 8), tg(D_/32, D_/32);

    split_plain<<<(n4 + 255)/256, 256>>>(x, xhi, xlo, n4);
    split_transpose<<<tg, tb>>>(Wq, whi + 0*(size_t)D_*D_, wlo + 0*(size_t)D_*D_);
    split_transpose<<<tg, tb>>>(Wk, whi + 1*(size_t)D_*D_, wlo + 1*(size_t)D_*D_);
    split_transpose<<<tg, tb>>>(Wv, whi + 2*(size_t)D_*D_, wlo + 2*(size_t)D_*D_);
    split_transpose<<<tg, tb>>>(Wo, whi + 3*(size_t)D_*D_, wlo + 3*(size_t)D_*D_);

    // fused QKV GEMM: N = 3072 (Wq^T | Wk^T | Wv^T contiguous)
    gemm_tc<4><<<dim3(3*D_/128, M_/128), 256, GSMEM>>>(
        xhi, xlo, whi, wlo, bq, bk, bv, nullptr);

    attn_tc<<<dim3(S_/128, B_*H_), 256, ATT_SMEM>>>();

    gemm_tc<0><<<dim3(D_/128, M_/128), 256, GSMEM>>>(
        aohi, aolo, whi + 3*(size_t)D_*D_, wlo + 3*(size_t)D_*D_, bo, nullptr, nullptr, out);
}

// round 7
// speedup vs baseline: 2.9536x; 1.0702x over previous
#include <cuda_runtime.h>
#include <cuda_bf16.h>
#include <stdint.h>
#include <math.h>

#define B_  2
#define S_  2048
#define D_  1024
#define H_  16
#define HD_ 64
#define M_  (B_*S_)        // 4096 rows

// ---------------------------------------------------------------------------
// Scratch (__device__ globals; no allocs allowed)
// ---------------------------------------------------------------------------
__device__ __nv_bfloat16 g_qhi[B_*H_*S_*HD_], g_qlo[B_*H_*S_*HD_];   // [B,H,S,HD]
__device__ __nv_bfloat16 g_khi[B_*H_*S_*HD_], g_klo[B_*H_*S_*HD_];
__device__ __nv_bfloat16 g_vhi[B_*H_*S_*HD_], g_vlo[B_*H_*S_*HD_];
__device__ __nv_bfloat16 g_aohi[M_*D_], g_aolo[M_*D_];               // [B,S,D]
__device__ __nv_bfloat16 g_xhi[M_*D_],  g_xlo[M_*D_];                // x split
__device__ __nv_bfloat16 g_whi[4][D_*D_], g_wlo[4][D_*D_];           // W^T splits

// ---------------------------------------------------------------------------
// PTX primitives (all baseline, valid on compute_103)
// ---------------------------------------------------------------------------
__device__ __forceinline__ void mma16816(float* c, const uint32_t* a, const uint32_t* b)
{
    asm volatile("mma.sync.aligned.m16n8k16.row.col.f32.bf16.bf16.f32 "
        "{%0,%1,%2,%3}, {%4,%5,%6,%7}, {%8,%9}, {%0,%1,%2,%3};"
        : "+f"(c[0]), "+f"(c[1]), "+f"(c[2]), "+f"(c[3])
        : "r"(a[0]), "r"(a[1]), "r"(a[2]), "r"(a[3]), "r"(b[0]), "r"(b[1]));
}

__device__ __forceinline__ uint32_t smem_u32(const void* p) {
    uint32_t a;
    asm("{ .reg .u64 t; cvta.to.shared.u64 t, %1; cvt.u32.u64 %0, t; }" : "=r"(a) : "l"(p));
    return a;
}

__device__ __forceinline__ void ldm_x4(uint32_t& r0, uint32_t& r1, uint32_t& r2,
                                       uint32_t& r3, uint32_t addr) {
    asm volatile("ldmatrix.sync.aligned.m8n8.x4.shared.b16 {%0,%1,%2,%3}, [%4];"
        : "=r"(r0), "=r"(r1), "=r"(r2), "=r"(r3) : "r"(addr));
}

__device__ __forceinline__ void cp16(uint32_t s, const void* g) {
    asm volatile("cp.async.cg.shared.global [%0], [%1], 16;" :: "r"(s), "l"(g));
}
#define CP_COMMIT() asm volatile("cp.async.commit_group;" ::: "memory")
#define CP_WAIT1()  asm volatile("cp.async.wait_group 1;" ::: "memory")
#define CP_WAIT0()  asm volatile("cp.async.wait_group 0;" ::: "memory")

// split helpers
__device__ __forceinline__ void split2(float v0, float v1, uint32_t& hi, uint32_t& lo) {
    __nv_bfloat16 h0 = __float2bfloat16_rn(v0), h1 = __float2bfloat16_rn(v1);
    __nv_bfloat16 l0 = __float2bfloat16_rn(v0 - __bfloat162float(h0));
    __nv_bfloat16 l1 = __float2bfloat16_rn(v1 - __bfloat162float(h1));
    __nv_bfloat162 h = __nv_bfloat162(h0, h1), l = __nv_bfloat162(l0, l1);
    hi = *(uint32_t*)&h; lo = *(uint32_t*)&l;
}

// ---------------------------------------------------------------------------
// Split kernels for the GEMM inputs
// ---------------------------------------------------------------------------
__global__ void split_plain(const float* __restrict__ in, __nv_bfloat16* __restrict__ hi,
                            __nv_bfloat16* __restrict__ lo, int n4)
{
    int i = blockIdx.x * blockDim.x + threadIdx.x;
    if (i >= n4) return;
    float4 a = ((const float4*)in)[i];
    uint32_t h0, l0, h1, l1;
    split2(a.x, a.y, h0, l0);
    split2(a.z, a.w, h1, l1);
    ((uint32_t*)hi)[2*i] = h0; ((uint32_t*)hi)[2*i+1] = h1;
    ((uint32_t*)lo)[2*i] = l0; ((uint32_t*)lo)[2*i+1] = l1;
}

// All 4 weights in one launch: blockIdx.z picks the W; writes g_whi[z]/g_wlo[z].
__global__ void split_transpose4(const float* __restrict__ W0, const float* __restrict__ W1,
                                 const float* __restrict__ W2, const float* __restrict__ W3)
{
    __shared__ float t[32][33];
    const int z = blockIdx.z;
    const float* in = (z == 0) ? W0 : (z == 1) ? W1 : (z == 2) ? W2 : W3;
    __nv_bfloat16* hi = g_whi[z];
    __nv_bfloat16* lo = g_wlo[z];
    const int k0 = blockIdx.y * 32, n0 = blockIdx.x * 32;
    const int tx = threadIdx.x, ty = threadIdx.y;   // 32 x 8
#pragma unroll
    for (int i = 0; i < 32; i += 8)
        t[ty + i][tx] = in[(size_t)(k0 + ty + i) * D_ + n0 + tx];
    __syncthreads();
#pragma unroll
    for (int i = 0; i < 32; i += 8) {
        float a = t[tx][ty + i];
        __nv_bfloat16 h = __float2bfloat16_rn(a);
        __nv_bfloat16 l = __float2bfloat16_rn(a - __bfloat162float(h));
        hi[(size_t)(n0 + ty + i) * D_ + k0 + tx] = h;
        lo[(size_t)(n0 + ty + i) * D_ + k0 + tx] = l;
    }
}

// ---------------------------------------------------------------------------
// HMMA GEMM, cp.async 3-stage + ldmatrix frags. C = A[M,K] x B[N,K]^T (split).
// MODE 0: fp32 + bias(b0) -> Cout.
// MODE 4: fused QKV (N=3072): which = bN>>10 picks bias b0/b1/b2 and the
//         q/k/v hi-lo destination. Q output is pre-scaled by 1/sqrt(HD).
// ---------------------------------------------------------------------------
#define LDSG   40
#define GSTAGE (128 * LDSG)                // elems per matrix per stage
#define GSMEM  (3 * 2 * GSTAGE * 2)        // bytes (3 stages x A,B x bf16)
#define NKIT   96                          // 3 phases x (1024/32)

template<int MODE>
__global__ void __launch_bounds__(256, 2)
gemm_tc(const __nv_bfloat16* __restrict__ Ahi, const __nv_bfloat16* __restrict__ Alo,
        const __nv_bfloat16* __restrict__ Bhi, const __nv_bfloat16* __restrict__ Blo,
        const float* __restrict__ b0, const float* __restrict__ b1,
        const float* __restrict__ b2, float* __restrict__ Cout)
{
    extern __shared__ __nv_bfloat16 sg[];
    const uint32_t smb = smem_u32(sg);

    const int tid  = threadIdx.x;
    const int wid  = tid >> 5, lane = tid & 31;
    const int g    = lane >> 2, t4 = lane & 3;
    const int r8   = lane & 7,  grp = lane >> 3;
    const int wm   = (wid >> 2) * 64;
    const int wn   = (wid & 3) * 32;
    const int bM   = blockIdx.y * 128, bN = blockIdx.x * 128;

    const int rowL = tid >> 1;
    const int colL = (tid & 1) * 16;       // 0 or 16 (two 16B chunks each)
    const size_t aRow = (size_t)(bM + rowL) * D_;
    const size_t bRow = (size_t)(bN + rowL) * D_;

    auto srcA = [&](int kc) { return (kc < 64) ? Ahi : Alo; };
    auto srcB = [&](int kc) { return (kc >= 32 && kc < 64) ? Blo : Bhi; };
    auto koff = [&](int kc) { return (size_t)(kc & 31) * 32; };

    const uint32_t sAld = smb + 2u * (rowL * LDSG + colL);
    const uint32_t sBld = smb + 2u * (3 * GSTAGE + rowL * LDSG + colL);

    auto issue = [&](int kc) {
        const int st = kc % 3;
        const __nv_bfloat16* A  = srcA(kc);
        const __nv_bfloat16* Bp = srcB(kc);
        const size_t k0 = koff(kc);
        const uint32_t sa = sAld + 2u * st * GSTAGE;
        const uint32_t sb = sBld + 2u * st * GSTAGE;
        cp16(sa,      A  + aRow + k0 + colL);
        cp16(sa + 16, A  + aRow + k0 + colL + 8);
        cp16(sb,      Bp + bRow + k0 + colL);
        cp16(sb + 16, Bp + bRow + k0 + colL + 8);
        CP_COMMIT();
    };

    float acc[4][4][4];
#pragma unroll
    for (int mi = 0; mi < 4; mi++)
#pragma unroll
        for (int ni = 0; ni < 4; ni++)
#pragma unroll
            for (int r = 0; r < 4; r++) acc[mi][ni][r] = 0.f;

    issue(0);
    issue(1);

    for (int kc = 0; kc < NKIT; kc++) {
        const int st = kc % 3;
        CP_WAIT1();
        __syncthreads();
        const uint32_t sAb = smb + 2u * (st * GSTAGE);
        const uint32_t sBb = smb + 2u * (3 * GSTAGE + st * GSTAGE);

#pragma unroll
        for (int ks = 0; ks < 2; ks++) {
            const int k0 = ks * 16;
            uint32_t af[4][4];
#pragma unroll
            for (int mi = 0; mi < 4; mi++) {
                const int row = wm + mi * 16 + r8 + (grp & 1) * 8;
                const int col = k0 + (grp >> 1) * 8;
                ldm_x4(af[mi][0], af[mi][1], af[mi][2], af[mi][3],
                       sAb + 2u * (row * LDSG + col));
            }
            uint32_t bf[4][2];
#pragma unroll
            for (int p = 0; p < 2; p++) {
                const int row = wn + p * 16 + r8 + (grp >> 1) * 8;
                const int col = k0 + (grp & 1) * 8;
                ldm_x4(bf[2*p][0], bf[2*p][1], bf[2*p+1][0], bf[2*p+1][1],
                       sBb + 2u * (row * LDSG + col));
            }
#pragma unroll
            for (int mi = 0; mi < 4; mi++)
#pragma unroll
                for (int ni = 0; ni < 4; ni++)
                    mma16816(acc[mi][ni], af[mi], bf[ni]);
        }
        if (kc + 2 < NKIT) issue(kc + 2);
    }

    // ---- epilogue ----
    const float* bias;
    __nv_bfloat16 *Gh = nullptr, *Gl = nullptr;
    int nBase = bN;
    float oscale = 1.f;
    if (MODE == 4) {
        const int which = bN >> 10;
        bias = (which == 0) ? b0 : (which == 1) ? b1 : b2;
        Gh = (which == 0) ? g_qhi : (which == 1) ? g_khi : g_vhi;
        Gl = (which == 0) ? g_qlo : (which == 1) ? g_klo : g_vlo;
        nBase = bN & 1023;
        if (which == 0) oscale = 0.125f;   // fold 1/sqrt(HD) into Q
    } else {
        bias = b0;
    }

#pragma unroll
    for (int mi = 0; mi < 4; mi++) {
#pragma unroll
        for (int hm = 0; hm < 2; hm++) {
            const int m = bM + wm + mi * 16 + g + hm * 8;
#pragma unroll
            for (int ni = 0; ni < 4; ni++) {
                const int nl = nBase + wn + ni * 8 + t4 * 2;
                float v0 = acc[mi][ni][hm * 2 + 0] + bias[nl];
                float v1 = acc[mi][ni][hm * 2 + 1] + bias[nl + 1];
                if (MODE == 0) {
                    *(float2*)(Cout + (size_t)m * D_ + nl) = make_float2(v0, v1);
                } else {
                    v0 *= oscale; v1 *= oscale;
                    const int bb = m >> 11, ss = m & (S_ - 1);
                    const int h = nl >> 6, hd = nl & 63;
                    const size_t o = (((size_t)(bb * H_ + h) * S_ + ss) << 6) + hd;
                    uint32_t hi, lo;
                    split2(v0, v1, hi, lo);
                    *(uint32_t*)(Gh + o) = hi;
                    *(uint32_t*)(Gl + o) = lo;
                }
            }
        }
    }
}

// ---------------------------------------------------------------------------
// Tensor-core flash attention, cp.async double-buffered K/V.
// Q pre-scaled by 1/sqrt(HD) at projection time.
// ---------------------------------------------------------------------------
#define PAD 72
#define KVSTAGE (4 * 64 * PAD)            // elems per stage (Khi,Klo,Vhi,Vlo)
#define ATT_SMEM (2 * KVSTAGE * 2)        // 73728 bytes
#define NT (S_ / 64)

__global__ void __launch_bounds__(256, 1)
attn_tc()
{
    extern __shared__ __nv_bfloat16 sm[];
    const uint32_t smb = smem_u32(sm);

    const int tid  = threadIdx.x;
    const int wid  = tid >> 5, lane = tid & 31;
    const int g    = lane >> 2, t4 = lane & 3;
    const int r8   = lane & 7,  grp = lane >> 3;
    const int q0   = blockIdx.x * 128;
    const int bh   = blockIdx.y;
    const int b    = bh >> 4, h = bh & 15;

    const size_t bhOff = (size_t)bh * (S_ * HD_);
    const __nv_bfloat16* Qh = g_qhi + bhOff + (size_t)q0 * HD_;
    const __nv_bfloat16* Ql = g_qlo + bhOff + (size_t)q0 * HD_;
    const __nv_bfloat16* Kh = g_khi + bhOff;
    const __nv_bfloat16* Kl = g_klo + bhOff;
    const __nv_bfloat16* Vh = g_vhi + bhOff;
    const __nv_bfloat16* Vl = g_vlo + bhOff;

    // ---- stage Q (uses stage-0/1 area; consumed before K/V loads) ----
#pragma unroll
    for (int i = 0; i < 4; i++) {
        const int idx = tid + i * 256;
        const int row = idx >> 3, c8 = (idx & 7) * 8;
        *(uint4*)&sm[row * PAD + c8]             = *(const uint4*)(Qh + row * HD_ + c8);
        *(uint4*)&sm[128 * PAD + row * PAD + c8] = *(const uint4*)(Ql + row * HD_ + c8);
    }
    __syncthreads();

    uint32_t qh[4][4], ql[4][4];
    {
#pragma unroll
        for (int kc = 0; kc < 4; kc++) {
            const int row = wid * 16 + r8 + (grp & 1) * 8;
            const int col = kc * 16 + (grp >> 1) * 8;
            ldm_x4(qh[kc][0], qh[kc][1], qh[kc][2], qh[kc][3],
                   smb + 2u * (row * PAD + col));
            ldm_x4(ql[kc][0], ql[kc][1], ql[kc][2], ql[kc][3],
                   smb + 2u * (128 * PAD + row * PAD + col));
        }
    }
    __syncthreads();   // Q fully in registers; smem now free for K/V stages

    // per-thread K/V cp.async pattern
    const int rowKV = tid >> 3, c8KV = (tid & 7) * 8;   // rows 0..31
    auto issueKV = [&](int kt) {
        const uint32_t base = (kt & 1) * KVSTAGE;
#pragma unroll
        for (int i = 0; i < 2; i++) {
            const int row = rowKV + i * 32;
            const size_t gidx = (size_t)(kt * 64 + row) * HD_ + c8KV;
            const uint32_t so = base + row * PAD + c8KV;
            cp16(smb + 2u * so,                 Kh + gidx);
            cp16(smb + 2u * (so +     64*PAD),  Kl + gidx);
            cp16(smb + 2u * (so + 2 * 64*PAD),  Vh + gidx);
            cp16(smb + 2u * (so + 3 * 64*PAD),  Vl + gidx);
        }
        CP_COMMIT();
    };

    float o[8][4];
#pragma unroll
    for (int j = 0; j < 8; j++)
#pragma unroll
        for (int r = 0; r < 4; r++) o[j][r] = 0.f;
    float m0 = -1e30f, m1 = -1e30f, l0 = 0.f, l1 = 0.f;

    issueKV(0);

    for (int kt = 0; kt < NT; kt++) {
        if (kt + 1 < NT) { issueKV(kt + 1); CP_WAIT1(); }
        else             { CP_WAIT0(); }
        __syncthreads();

        const int stB = (kt & 1) * KVSTAGE;
        const int KHI = stB, KLO = stB + 64*PAD, VHI = stB + 2*64*PAD, VLO = stB + 3*64*PAD;

        // ---- S = Q K^T (3-pass, K frags via ldmatrix); Q pre-scaled ----
        float c[8][4];
#pragma unroll
        for (int j = 0; j < 8; j++)
#pragma unroll
            for (int r = 0; r < 4; r++) c[j][r] = 0.f;

#pragma unroll
        for (int kc = 0; kc < 4; kc++) {
#pragma unroll
            for (int p = 0; p < 4; p++) {
                const int row = p * 16 + r8 + (grp >> 1) * 8;
                const int col = kc * 16 + (grp & 1) * 8;
                uint32_t bhA[2], bhB[2], blA[2], blB[2];
                ldm_x4(bhA[0], bhA[1], bhB[0], bhB[1],
                       smb + 2u * (KHI + row * PAD + col));
                ldm_x4(blA[0], blA[1], blB[0], blB[1],
                       smb + 2u * (KLO + row * PAD + col));
                mma16816(c[2*p],   qh[kc], bhA);
                mma16816(c[2*p],   qh[kc], blA);
                mma16816(c[2*p],   ql[kc], bhA);
                mma16816(c[2*p+1], qh[kc], bhB);
                mma16816(c[2*p+1], qh[kc], blB);
                mma16816(c[2*p+1], ql[kc], bhB);
            }
        }

        // ---- online softmax (rows g and g+8, warp-local quads) ----
        float mx0 = -1e30f, mx1 = -1e30f;
#pragma unroll
        for (int j = 0; j < 8; j++) {
            mx0 = fmaxf(mx0, fmaxf(c[j][0], c[j][1]));
            mx1 = fmaxf(mx1, fmaxf(c[j][2], c[j][3]));
        }
#pragma unroll
        for (int off = 1; off <= 2; off <<= 1) {
            mx0 = fmaxf(mx0, __shfl_xor_sync(0xffffffffu, mx0, off));
            mx1 = fmaxf(mx1, __shfl_xor_sync(0xffffffffu, mx1, off));
        }
        const float nm0 = fmaxf(m0, mx0), nm1 = fmaxf(m1, mx1);
        const float cr0 = __expf(m0 - nm0), cr1 = __expf(m1 - nm1);
        float rs0 = 0.f, rs1 = 0.f;
#pragma unroll
        for (int j = 0; j < 8; j++) {
            c[j][0] = __expf(c[j][0] - nm0);
            c[j][1] = __expf(c[j][1] - nm0);
            c[j][2] = __expf(c[j][2] - nm1);
            c[j][3] = __expf(c[j][3] - nm1);
            rs0 += c[j][0] + c[j][1];
            rs1 += c[j][2] + c[j][3];
        }
#pragma unroll
        for (int off = 1; off <= 2; off <<= 1) {
            rs0 += __shfl_xor_sync(0xffffffffu, rs0, off);
            rs1 += __shfl_xor_sync(0xffffffffu, rs1, off);
        }
        l0 = l0 * cr0 + rs0;  m0 = nm0;
        l1 = l1 * cr1 + rs1;  m1 = nm1;
#pragma unroll
        for (int j = 0; j < 8; j++) {
            o[j][0] *= cr0; o[j][1] *= cr0;
            o[j][2] *= cr1; o[j][3] *= cr1;
        }

        // ---- O += P V (3-pass; P split in-register; V via ldmatrix.trans) ----
#pragma unroll
        for (int kc = 0; kc < 4; kc++) {
            uint32_t ah[4], al[4];
            split2(c[2*kc  ][0], c[2*kc  ][1], ah[0], al[0]);
            split2(c[2*kc  ][2], c[2*kc  ][3], ah[1], al[1]);
            split2(c[2*kc+1][0], c[2*kc+1][1], ah[2], al[2]);
            split2(c[2*kc+1][2], c[2*kc+1][3], ah[3], al[3]);

            const int r = lane >> 3, i = lane & 7;
            const int vrow = kc * 16 + (r & 1) * 8 + i;
            const int vcolp = (r >> 1) * 8;

            uint32_t vb[4][4];
#pragma unroll
            for (int np = 0; np < 4; np++) {
                const uint32_t addr = smb + 2u * (uint32_t)(VHI + vrow * PAD + np * 16 + vcolp);
                asm volatile("ldmatrix.sync.aligned.m8n8.x4.trans.shared.b16 {%0,%1,%2,%3}, [%4];"
                    : "=r"(vb[np][0]), "=r"(vb[np][1]), "=r"(vb[np][2]), "=r"(vb[np][3])
                    : "r"(addr));
            }
#pragma unroll
            for (int nt = 0; nt < 8; nt++) {
                uint32_t bb[2] = { vb[nt >> 1][(nt & 1) * 2], vb[nt >> 1][(nt & 1) * 2 + 1] };
                mma16816(o[nt], ah, bb);
                mma16816(o[nt], al, bb);
            }
#pragma unroll
            for (int np = 0; np < 4; np++) {
                const uint32_t addr = smb + 2u * (uint32_t)(VLO + vrow * PAD + np * 16 + vcolp);
                asm volatile("ldmatrix.sync.aligned.m8n8.x4.trans.shared.b16 {%0,%1,%2,%3}, [%4];"
                    : "=r"(vb[np][0]), "=r"(vb[np][1]), "=r"(vb[np][2]), "=r"(vb[np][3])
                    : "r"(addr));
            }
#pragma unroll
            for (int nt = 0; nt < 8; nt++) {
                uint32_t bb[2] = { vb[nt >> 1][(nt & 1) * 2], vb[nt >> 1][(nt & 1) * 2 + 1] };
                mma16816(o[nt], ah, bb);
            }
        }
        __syncthreads();
    }

    // ---- epilogue: normalize, split, write [B,S,D] bf16 hi/lo ----
    const float inv0 = 1.f / l0, inv1 = 1.f / l1;
    const int row0 = q0 + wid * 16 + g;
#pragma unroll
    for (int j = 0; j < 8; j++) {
        const int d = h * HD_ + j * 8 + t4 * 2;
        uint32_t hi, lo;
        split2(o[j][0] * inv0, o[j][1] * inv0, hi, lo);
        const size_t o0 = (size_t)(b * S_ + row0) * D_ + d;
        *(uint32_t*)(g_aohi + o0) = hi;
        *(uint32_t*)(g_aolo + o0) = lo;
        split2(o[j][2] * inv1, o[j][3] * inv1, hi, lo);
        const size_t o1 = (size_t)(b * S_ + row0 + 8) * D_ + d;
        *(uint32_t*)(g_aohi + o1) = hi;
        *(uint32_t*)(g_aolo + o1) = lo;
    }
}

// ---------------------------------------------------------------------------

extern "C" void kernel_launch(void* const* d_in, const int* in_sizes, int n_in,
                              void* d_out, int out_size)
{
    const float* x  = (const float*)d_in[0];
    const float* Wq = (const float*)d_in[1];
    const float* bq = (const float*)d_in[2];
    const float* Wk = (const float*)d_in[3];
    const float* bk = (const float*)d_in[4];
    const float* Wv = (const float*)d_in[5];
    const float* bv = (const float*)d_in[6];
    const float* Wo = (const float*)d_in[7];
    const float* bo = (const float*)d_in[8];
    float* out = (float*)d_out;

    void *p_xhi, *p_xlo, *p_aohi, *p_aolo, *p_whi, *p_wlo;
    cudaGetSymbolAddress(&p_xhi,  g_xhi);
    cudaGetSymbolAddress(&p_xlo,  g_xlo);
    cudaGetSymbolAddress(&p_aohi, g_aohi);
    cudaGetSymbolAddress(&p_aolo, g_aolo);
    cudaGetSymbolAddress(&p_whi,  g_whi);
    cudaGetSymbolAddress(&p_wlo,  g_wlo);
    __nv_bfloat16* xhi  = (__nv_bfloat16*)p_xhi;
    __nv_bfloat16* xlo  = (__nv_bfloat16*)p_xlo;
    __nv_bfloat16* aohi = (__nv_bfloat16*)p_aohi;
    __nv_bfloat16* aolo = (__nv_bfloat16*)p_aolo;
    __nv_bfloat16* whi  = (__nv_bfloat16*)p_whi;
    __nv_bfloat16* wlo  = (__nv_bfloat16*)p_wlo;

    cudaFuncSetAttribute(attn_tc,
                         cudaFuncAttributeMaxDynamicSharedMemorySize, ATT_SMEM);
    cudaFuncSetAttribute(gemm_tc<0>, cudaFuncAttributeMaxDynamicSharedMemorySize, GSMEM);
    cudaFuncSetAttribute(gemm_tc<4>, cudaFuncAttributeMaxDynamicSharedMemorySize, GSMEM);

    const int n4 = M_ * D_ / 4;

    split_plain<<<(n4 + 255)/256, 256>>>(x, xhi, xlo, n4);
    split_transpose4<<<dim3(D_/32, D_/32, 4), dim3(32, 8)>>>(Wq, Wk, Wv, Wo);

    // fused QKV GEMM: N = 3072 (Wq^T | Wk^T | Wv^T contiguous)
    gemm_tc<4><<<dim3(3*D_/128, M_/128), 256, GSMEM>>>(
        xhi, xlo, whi, wlo, bq, bk, bv, nullptr);

    attn_tc<<<dim3(S_/128, B_*H_), 256, ATT_SMEM>>>();

    gemm_tc<0><<<dim3(D_/128, M_/128), 256, GSMEM>>>(
        aohi, aolo, whi + 3*(size_t)D_*D_, wlo + 3*(size_t)D_*D_, bo, nullptr, nullptr, out);
}

// round 8
// speedup vs baseline: 3.1515x; 1.0670x over previous
#include <cuda_runtime.h>
#include <cuda_bf16.h>
#include <stdint.h>
#include <math.h>

#define B_  2
#define S_  2048
#define D_  1024
#define H_  16
#define HD_ 64
#define M_  (B_*S_)        // 4096 rows

// ---------------------------------------------------------------------------
// Scratch (__device__ globals; no allocs allowed)
// ---------------------------------------------------------------------------
__device__ __nv_bfloat16 g_qhi[B_*H_*S_*HD_], g_qlo[B_*H_*S_*HD_];   // [B,H,S,HD]
__device__ __nv_bfloat16 g_khi[B_*H_*S_*HD_], g_klo[B_*H_*S_*HD_];
__device__ __nv_bfloat16 g_vhi[B_*H_*S_*HD_], g_vlo[B_*H_*S_*HD_];
__device__ __nv_bfloat16 g_aohi[M_*D_], g_aolo[M_*D_];               // [B,S,D]
__device__ __nv_bfloat16 g_xhi[M_*D_],  g_xlo[M_*D_];                // x split
__device__ __nv_bfloat16 g_whi[4][D_*D_], g_wlo[4][D_*D_];           // W^T splits

// ---------------------------------------------------------------------------
// PTX primitives (all baseline, valid on compute_103)
// ---------------------------------------------------------------------------
__device__ __forceinline__ void mma16816(float* c, const uint32_t* a, const uint32_t* b)
{
    asm volatile("mma.sync.aligned.m16n8k16.row.col.f32.bf16.bf16.f32 "
        "{%0,%1,%2,%3}, {%4,%5,%6,%7}, {%8,%9}, {%0,%1,%2,%3};"
        : "+f"(c[0]), "+f"(c[1]), "+f"(c[2]), "+f"(c[3])
        : "r"(a[0]), "r"(a[1]), "r"(a[2]), "r"(a[3]), "r"(b[0]), "r"(b[1]));
}

__device__ __forceinline__ uint32_t smem_u32(const void* p) {
    uint32_t a;
    asm("{ .reg .u64 t; cvta.to.shared.u64 t, %1; cvt.u32.u64 %0, t; }" : "=r"(a) : "l"(p));
    return a;
}

__device__ __forceinline__ void ldm_x4(uint32_t& r0, uint32_t& r1, uint32_t& r2,
                                       uint32_t& r3, uint32_t addr) {
    asm volatile("ldmatrix.sync.aligned.m8n8.x4.shared.b16 {%0,%1,%2,%3}, [%4];"
        : "=r"(r0), "=r"(r1), "=r"(r2), "=r"(r3) : "r"(addr));
}

__device__ __forceinline__ void cp16(uint32_t s, const void* g) {
    asm volatile("cp.async.cg.shared.global [%0], [%1], 16;" :: "r"(s), "l"(g));
}
#define CP_COMMIT() asm volatile("cp.async.commit_group;" ::: "memory")
#define CP_WAIT1()  asm volatile("cp.async.wait_group 1;" ::: "memory")
#define CP_WAIT0()  asm volatile("cp.async.wait_group 0;" ::: "memory")

// split helpers
__device__ __forceinline__ void split2(float v0, float v1, uint32_t& hi, uint32_t& lo) {
    __nv_bfloat16 h0 = __float2bfloat16_rn(v0), h1 = __float2bfloat16_rn(v1);
    __nv_bfloat16 l0 = __float2bfloat16_rn(v0 - __bfloat162float(h0));
    __nv_bfloat16 l1 = __float2bfloat16_rn(v1 - __bfloat162float(h1));
    __nv_bfloat162 h = __nv_bfloat162(h0, h1), l = __nv_bfloat162(l0, l1);
    hi = *(uint32_t*)&h; lo = *(uint32_t*)&l;
}

// ---------------------------------------------------------------------------
// Split kernels for the GEMM inputs
// ---------------------------------------------------------------------------
__global__ void split_plain(const float* __restrict__ in, __nv_bfloat16* __restrict__ hi,
                            __nv_bfloat16* __restrict__ lo, int n4)
{
    int i = blockIdx.x * blockDim.x + threadIdx.x;
    if (i >= n4) return;
    float4 a = ((const float4*)in)[i];
    uint32_t h0, l0, h1, l1;
    split2(a.x, a.y, h0, l0);
    split2(a.z, a.w, h1, l1);
    ((uint32_t*)hi)[2*i] = h0; ((uint32_t*)hi)[2*i+1] = h1;
    ((uint32_t*)lo)[2*i] = l0; ((uint32_t*)lo)[2*i+1] = l1;
}

// All 4 weights in one launch: blockIdx.z picks the W; writes g_whi[z]/g_wlo[z].
__global__ void split_transpose4(const float* __restrict__ W0, const float* __restrict__ W1,
                                 const float* __restrict__ W2, const float* __restrict__ W3)
{
    __shared__ float t[32][33];
    const int z = blockIdx.z;
    const float* in = (z == 0) ? W0 : (z == 1) ? W1 : (z == 2) ? W2 : W3;
    __nv_bfloat16* hi = g_whi[z];
    __nv_bfloat16* lo = g_wlo[z];
    const int k0 = blockIdx.y * 32, n0 = blockIdx.x * 32;
    const int tx = threadIdx.x, ty = threadIdx.y;   // 32 x 8
#pragma unroll
    for (int i = 0; i < 32; i += 8)
        t[ty + i][tx] = in[(size_t)(k0 + ty + i) * D_ + n0 + tx];
    __syncthreads();
#pragma unroll
    for (int i = 0; i < 32; i += 8) {
        float a = t[tx][ty + i];
        __nv_bfloat16 h = __float2bfloat16_rn(a);
        __nv_bfloat16 l = __float2bfloat16_rn(a - __bfloat162float(h));
        hi[(size_t)(n0 + ty + i) * D_ + k0 + tx] = h;
        lo[(size_t)(n0 + ty + i) * D_ + k0 + tx] = l;
    }
}

// ---------------------------------------------------------------------------
// HMMA GEMM, cp.async 3-stage + ldmatrix frags. C = A[M,K] x B[N,K]^T (split).
// MODE 0: fp32 + bias(b0) -> Cout.
// MODE 4: fused QKV (N=3072): which = bN>>10 picks bias b0/b1/b2 and the
//         q/k/v hi-lo destination. Q output is pre-scaled by 1/sqrt(HD).
// ---------------------------------------------------------------------------
#define LDSG   40
#define GSTAGE (128 * LDSG)                // elems per matrix per stage
#define GSMEM  (3 * 2 * GSTAGE * 2)        // bytes (3 stages x A,B x bf16)
#define NKIT   96                          // 3 phases x (1024/32)

template<int MODE>
__global__ void __launch_bounds__(256, 2)
gemm_tc(const __nv_bfloat16* __restrict__ Ahi, const __nv_bfloat16* __restrict__ Alo,
        const __nv_bfloat16* __restrict__ Bhi, const __nv_bfloat16* __restrict__ Blo,
        const float* __restrict__ b0, const float* __restrict__ b1,
        const float* __restrict__ b2, float* __restrict__ Cout)
{
    extern __shared__ __nv_bfloat16 sg[];
    const uint32_t smb = smem_u32(sg);

    const int tid  = threadIdx.x;
    const int wid  = tid >> 5, lane = tid & 31;
    const int g    = lane >> 2, t4 = lane & 3;
    const int r8   = lane & 7,  grp = lane >> 3;
    const int wm   = (wid >> 2) * 64;
    const int wn   = (wid & 3) * 32;
    const int bM   = blockIdx.y * 128, bN = blockIdx.x * 128;

    const int rowL = tid >> 1;
    const int colL = (tid & 1) * 16;       // 0 or 16 (two 16B chunks each)
    const size_t aRow = (size_t)(bM + rowL) * D_;
    const size_t bRow = (size_t)(bN + rowL) * D_;

    auto srcA = [&](int kc) { return (kc < 64) ? Ahi : Alo; };
    auto srcB = [&](int kc) { return (kc >= 32 && kc < 64) ? Blo : Bhi; };
    auto koff = [&](int kc) { return (size_t)(kc & 31) * 32; };

    const uint32_t sAld = smb + 2u * (rowL * LDSG + colL);
    const uint32_t sBld = smb + 2u * (3 * GSTAGE + rowL * LDSG + colL);

    auto issue = [&](int kc) {
        const int st = kc % 3;
        const __nv_bfloat16* A  = srcA(kc);
        const __nv_bfloat16* Bp = srcB(kc);
        const size_t k0 = koff(kc);
        const uint32_t sa = sAld + 2u * st * GSTAGE;
        const uint32_t sb = sBld + 2u * st * GSTAGE;
        cp16(sa,      A  + aRow + k0 + colL);
        cp16(sa + 16, A  + aRow + k0 + colL + 8);
        cp16(sb,      Bp + bRow + k0 + colL);
        cp16(sb + 16, Bp + bRow + k0 + colL + 8);
        CP_COMMIT();
    };

    float acc[4][4][4];
#pragma unroll
    for (int mi = 0; mi < 4; mi++)
#pragma unroll
        for (int ni = 0; ni < 4; ni++)
#pragma unroll
            for (int r = 0; r < 4; r++) acc[mi][ni][r] = 0.f;

    issue(0);
    issue(1);

    for (int kc = 0; kc < NKIT; kc++) {
        const int st = kc % 3;
        CP_WAIT1();
        __syncthreads();
        const uint32_t sAb = smb + 2u * (st * GSTAGE);
        const uint32_t sBb = smb + 2u * (3 * GSTAGE + st * GSTAGE);

#pragma unroll
        for (int ks = 0; ks < 2; ks++) {
            const int k0 = ks * 16;
            uint32_t af[4][4];
#pragma unroll
            for (int mi = 0; mi < 4; mi++) {
                const int row = wm + mi * 16 + r8 + (grp & 1) * 8;
                const int col = k0 + (grp >> 1) * 8;
                ldm_x4(af[mi][0], af[mi][1], af[mi][2], af[mi][3],
                       sAb + 2u * (row * LDSG + col));
            }
            uint32_t bf[4][2];
#pragma unroll
            for (int p = 0; p < 2; p++) {
                const int row = wn + p * 16 + r8 + (grp >> 1) * 8;
                const int col = k0 + (grp & 1) * 8;
                ldm_x4(bf[2*p][0], bf[2*p][1], bf[2*p+1][0], bf[2*p+1][1],
                       sBb + 2u * (row * LDSG + col));
            }
#pragma unroll
            for (int mi = 0; mi < 4; mi++)
#pragma unroll
                for (int ni = 0; ni < 4; ni++)
                    mma16816(acc[mi][ni], af[mi], bf[ni]);
        }
        if (kc + 2 < NKIT) issue(kc + 2);
    }

    // ---- epilogue ----
    const float* bias;
    __nv_bfloat16 *Gh = nullptr, *Gl = nullptr;
    int nBase = bN;
    float oscale = 1.f;
    if (MODE == 4) {
        const int which = bN >> 10;
        bias = (which == 0) ? b0 : (which == 1) ? b1 : b2;
        Gh = (which == 0) ? g_qhi : (which == 1) ? g_khi : g_vhi;
        Gl = (which == 0) ? g_qlo : (which == 1) ? g_klo : g_vlo;
        nBase = bN & 1023;
        if (which == 0) oscale = 0.125f;   // fold 1/sqrt(HD) into Q
    } else {
        bias = b0;
    }

#pragma unroll
    for (int mi = 0; mi < 4; mi++) {
#pragma unroll
        for (int hm = 0; hm < 2; hm++) {
            const int m = bM + wm + mi * 16 + g + hm * 8;
#pragma unroll
            for (int ni = 0; ni < 4; ni++) {
                const int nl = nBase + wn + ni * 8 + t4 * 2;
                float v0 = acc[mi][ni][hm * 2 + 0] + bias[nl];
                float v1 = acc[mi][ni][hm * 2 + 1] + bias[nl + 1];
                if (MODE == 0) {
                    *(float2*)(Cout + (size_t)m * D_ + nl) = make_float2(v0, v1);
                } else {
                    v0 *= oscale; v1 *= oscale;
                    const int bb = m >> 11, ss = m & (S_ - 1);
                    const int h = nl >> 6, hd = nl & 63;
                    const size_t o = (((size_t)(bb * H_ + h) * S_ + ss) << 6) + hd;
                    uint32_t hi, lo;
                    split2(v0, v1, hi, lo);
                    *(uint32_t*)(Gh + o) = hi;
                    *(uint32_t*)(Gl + o) = lo;
                }
            }
        }
    }
}

// ---------------------------------------------------------------------------
// Tensor-core flash attention, cp.async double-buffered K/V.
// 64 queries per CTA, 4 warps (16q x 64k warp tile), 3 CTAs/SM so another
// CTA's MMAs cover this CTA's softmax (r7 showed tensor=52.8% @ occ 1).
// Q pre-scaled by 1/sqrt(HD) at projection time.
// ---------------------------------------------------------------------------
#define PAD 72
#define KVSTAGE (4 * 64 * PAD)            // elems per stage (Khi,Klo,Vhi,Vlo)
#define ATT_SMEM (2 * KVSTAGE * 2)        // 73728 bytes
#define NT (S_ / 64)

__global__ void __launch_bounds__(128, 3)
attn_tc()
{
    extern __shared__ __nv_bfloat16 sm[];
    const uint32_t smb = smem_u32(sm);

    const int tid  = threadIdx.x;
    const int wid  = tid >> 5, lane = tid & 31;
    const int g    = lane >> 2, t4 = lane & 3;
    const int r8   = lane & 7,  grp = lane >> 3;
    const int q0   = blockIdx.x * 64;
    const int bh   = blockIdx.y;
    const int b    = bh >> 4, h = bh & 15;

    const size_t bhOff = (size_t)bh * (S_ * HD_);
    const __nv_bfloat16* Qh = g_qhi + bhOff + (size_t)q0 * HD_;
    const __nv_bfloat16* Ql = g_qlo + bhOff + (size_t)q0 * HD_;
    const __nv_bfloat16* Kh = g_khi + bhOff;
    const __nv_bfloat16* Kl = g_klo + bhOff;
    const __nv_bfloat16* Vh = g_vhi + bhOff;
    const __nv_bfloat16* Vl = g_vlo + bhOff;

    // ---- stage Q (64 rows hi + 64 rows lo; uses stage area, consumed now) ----
#pragma unroll
    for (int i = 0; i < 4; i++) {
        const int idx = tid + i * 128;          // 0..511
        const int row = idx >> 3, c8 = (idx & 7) * 8;
        *(uint4*)&sm[row * PAD + c8]            = *(const uint4*)(Qh + row * HD_ + c8);
        *(uint4*)&sm[64 * PAD + row * PAD + c8] = *(const uint4*)(Ql + row * HD_ + c8);
    }
    __syncthreads();

    uint32_t qh[4][4], ql[4][4];
    {
#pragma unroll
        for (int kc = 0; kc < 4; kc++) {
            const int row = wid * 16 + r8 + (grp & 1) * 8;
            const int col = kc * 16 + (grp >> 1) * 8;
            ldm_x4(qh[kc][0], qh[kc][1], qh[kc][2], qh[kc][3],
                   smb + 2u * (row * PAD + col));
            ldm_x4(ql[kc][0], ql[kc][1], ql[kc][2], ql[kc][3],
                   smb + 2u * (64 * PAD + row * PAD + col));
        }
    }
    __syncthreads();   // Q fully in registers; smem now free for K/V stages

    // per-thread K/V cp.async pattern (128 threads, 64 rows x 8 chunks)
    const int rowKV = tid >> 3, c8KV = (tid & 7) * 8;   // rows 0..15
    auto issueKV = [&](int kt) {
        const uint32_t base = (kt & 1) * KVSTAGE;
#pragma unroll
        for (int i = 0; i < 4; i++) {
            const int row = rowKV + i * 16;
            const size_t gidx = (size_t)(kt * 64 + row) * HD_ + c8KV;
            const uint32_t so = base + row * PAD + c8KV;
            cp16(smb + 2u * so,                 Kh + gidx);
            cp16(smb + 2u * (so +     64*PAD),  Kl + gidx);
            cp16(smb + 2u * (so + 2 * 64*PAD),  Vh + gidx);
            cp16(smb + 2u * (so + 3 * 64*PAD),  Vl + gidx);
        }
        CP_COMMIT();
    };

    float o[8][4];
#pragma unroll
    for (int j = 0; j < 8; j++)
#pragma unroll
        for (int r = 0; r < 4; r++) o[j][r] = 0.f;
    float m0 = -1e30f, m1 = -1e30f, l0 = 0.f, l1 = 0.f;

    issueKV(0);

    for (int kt = 0; kt < NT; kt++) {
        if (kt + 1 < NT) { issueKV(kt + 1); CP_WAIT1(); }
        else             { CP_WAIT0(); }
        __syncthreads();

        const int stB = (kt & 1) * KVSTAGE;
        const int KHI = stB, KLO = stB + 64*PAD, VHI = stB + 2*64*PAD, VLO = stB + 3*64*PAD;

        // ---- S = Q K^T (3-pass, K frags via ldmatrix); Q pre-scaled ----
        float c[8][4];
#pragma unroll
        for (int j = 0; j < 8; j++)
#pragma unroll
            for (int r = 0; r < 4; r++) c[j][r] = 0.f;

#pragma unroll
        for (int kc = 0; kc < 4; kc++) {
#pragma unroll
            for (int p = 0; p < 4; p++) {
                const int row = p * 16 + r8 + (grp >> 1) * 8;
                const int col = kc * 16 + (grp & 1) * 8;
                uint32_t bhA[2], bhB[2], blA[2], blB[2];
                ldm_x4(bhA[0], bhA[1], bhB[0], bhB[1],
                       smb + 2u * (KHI + row * PAD + col));
                ldm_x4(blA[0], blA[1], blB[0], blB[1],
                       smb + 2u * (KLO + row * PAD + col));
                mma16816(c[2*p],   qh[kc], bhA);
                mma16816(c[2*p],   qh[kc], blA);
                mma16816(c[2*p],   ql[kc], bhA);
                mma16816(c[2*p+1], qh[kc], bhB);
                mma16816(c[2*p+1], qh[kc], blB);
                mma16816(c[2*p+1], ql[kc], bhB);
            }
        }

        // ---- online softmax (rows g and g+8, warp-local quads) ----
        float mx0 = -1e30f, mx1 = -1e30f;
#pragma unroll
        for (int j = 0; j < 8; j++) {
            mx0 = fmaxf(mx0, fmaxf(c[j][0], c[j][1]));
            mx1 = fmaxf(mx1, fmaxf(c[j][2], c[j][3]));
        }
#pragma unroll
        for (int off = 1; off <= 2; off <<= 1) {
            mx0 = fmaxf(mx0, __shfl_xor_sync(0xffffffffu, mx0, off));
            mx1 = fmaxf(mx1, __shfl_xor_sync(0xffffffffu, mx1, off));
        }
        const float nm0 = fmaxf(m0, mx0), nm1 = fmaxf(m1, mx1);
        const float cr0 = __expf(m0 - nm0), cr1 = __expf(m1 - nm1);
        float rs0 = 0.f, rs1 = 0.f;
#pragma unroll
        for (int j = 0; j < 8; j++) {
            c[j][0] = __expf(c[j][0] - nm0);
            c[j][1] = __expf(c[j][1] - nm0);
            c[j][2] = __expf(c[j][2] - nm1);
            c[j][3] = __expf(c[j][3] - nm1);
            rs0 += c[j][0] + c[j][1];
            rs1 += c[j][2] + c[j][3];
        }
#pragma unroll
        for (int off = 1; off <= 2; off <<= 1) {
            rs0 += __shfl_xor_sync(0xffffffffu, rs0, off);
            rs1 += __shfl_xor_sync(0xffffffffu, rs1, off);
        }
        l0 = l0 * cr0 + rs0;  m0 = nm0;
        l1 = l1 * cr1 + rs1;  m1 = nm1;
#pragma unroll
        for (int j = 0; j < 8; j++) {
            o[j][0] *= cr0; o[j][1] *= cr0;
            o[j][2] *= cr1; o[j][3] *= cr1;
        }

        // ---- O += P V (3-pass; P split in-register; V via ldmatrix.trans) ----
#pragma unroll
        for (int kc = 0; kc < 4; kc++) {
            uint32_t ah[4], al[4];
            split2(c[2*kc  ][0], c[2*kc  ][1], ah[0], al[0]);
            split2(c[2*kc  ][2], c[2*kc  ][3], ah[1], al[1]);
            split2(c[2*kc+1][0], c[2*kc+1][1], ah[2], al[2]);
            split2(c[2*kc+1][2], c[2*kc+1][3], ah[3], al[3]);

            const int r = lane >> 3, i = lane & 7;
            const int vrow = kc * 16 + (r & 1) * 8 + i;
            const int vcolp = (r >> 1) * 8;

            uint32_t vb[4][4];
#pragma unroll
            for (int np = 0; np < 4; np++) {
                const uint32_t addr = smb + 2u * (uint32_t)(VHI + vrow * PAD + np * 16 + vcolp);
                asm volatile("ldmatrix.sync.aligned.m8n8.x4.trans.shared.b16 {%0,%1,%2,%3}, [%4];"
                    : "=r"(vb[np][0]), "=r"(vb[np][1]), "=r"(vb[np][2]), "=r"(vb[np][3])
                    : "r"(addr));
            }
#pragma unroll
            for (int nt = 0; nt < 8; nt++) {
                uint32_t bb[2] = { vb[nt >> 1][(nt & 1) * 2], vb[nt >> 1][(nt & 1) * 2 + 1] };
                mma16816(o[nt], ah, bb);
                mma16816(o[nt], al, bb);
            }
#pragma unroll
            for (int np = 0; np < 4; np++) {
                const uint32_t addr = smb + 2u * (uint32_t)(VLO + vrow * PAD + np * 16 + vcolp);
                asm volatile("ldmatrix.sync.aligned.m8n8.x4.trans.shared.b16 {%0,%1,%2,%3}, [%4];"
                    : "=r"(vb[np][0]), "=r"(vb[np][1]), "=r"(vb[np][2]), "=r"(vb[np][3])
                    : "r"(addr));
            }
#pragma unroll
            for (int nt = 0; nt < 8; nt++) {
                uint32_t bb[2] = { vb[nt >> 1][(nt & 1) * 2], vb[nt >> 1][(nt & 1) * 2 + 1] };
                mma16816(o[nt], ah, bb);
            }
        }
        __syncthreads();
    }

    // ---- epilogue: normalize, split, write [B,S,D] bf16 hi/lo ----
    const float inv0 = 1.f / l0, inv1 = 1.f / l1;
    const int row0 = q0 + wid * 16 + g;
#pragma unroll
    for (int j = 0; j < 8; j++) {
        const int d = h * HD_ + j * 8 + t4 * 2;
        uint32_t hi, lo;
        split2(o[j][0] * inv0, o[j][1] * inv0, hi, lo);
        const size_t o0 = (size_t)(b * S_ + row0) * D_ + d;
        *(uint32_t*)(g_aohi + o0) = hi;
        *(uint32_t*)(g_aolo + o0) = lo;
        split2(o[j][2] * inv1, o[j][3] * inv1, hi, lo);
        const size_t o1 = (size_t)(b * S_ + row0 + 8) * D_ + d;
        *(uint32_t*)(g_aohi + o1) = hi;
        *(uint32_t*)(g_aolo + o1) = lo;
    }
}

// ---------------------------------------------------------------------------

extern "C" void kernel_launch(void* const* d_in, const int* in_sizes, int n_in,
                              void* d_out, int out_size)
{
    const float* x  = (const float*)d_in[0];
    const float* Wq = (const float*)d_in[1];
    const float* bq = (const float*)d_in[2];
    const float* Wk = (const float*)d_in[3];
    const float* bk = (const float*)d_in[4];
    const float* Wv = (const float*)d_in[5];
    const float* bv = (const float*)d_in[6];
    const float* Wo = (const float*)d_in[7];
    const float* bo = (const float*)d_in[8];
    float* out = (float*)d_out;

    void *p_xhi, *p_xlo, *p_aohi, *p_aolo, *p_whi, *p_wlo;
    cudaGetSymbolAddress(&p_xhi,  g_xhi);
    cudaGetSymbolAddress(&p_xlo,  g_xlo);
    cudaGetSymbolAddress(&p_aohi, g_aohi);
    cudaGetSymbolAddress(&p_aolo, g_aolo);
    cudaGetSymbolAddress(&p_whi,  g_whi);
    cudaGetSymbolAddress(&p_wlo,  g_wlo);
    __nv_bfloat16* xhi  = (__nv_bfloat16*)p_xhi;
    __nv_bfloat16* xlo  = (__nv_bfloat16*)p_xlo;
    __nv_bfloat16* aohi = (__nv_bfloat16*)p_aohi;
    __nv_bfloat16* aolo = (__nv_bfloat16*)p_aolo;
    __nv_bfloat16* whi  = (__nv_bfloat16*)p_whi;
    __nv_bfloat16* wlo  = (__nv_bfloat16*)p_wlo;

    cudaFuncSetAttribute(attn_tc,
                         cudaFuncAttributeMaxDynamicSharedMemorySize, ATT_SMEM);
    cudaFuncSetAttribute(gemm_tc<0>, cudaFuncAttributeMaxDynamicSharedMemorySize, GSMEM);
    cudaFuncSetAttribute(gemm_tc<4>, cudaFuncAttributeMaxDynamicSharedMemorySize, GSMEM);

    const int n4 = M_ * D_ / 4;

    split_plain<<<(n4 + 255)/256, 256>>>(x, xhi, xlo, n4);
    split_transpose4<<<dim3(D_/32, D_/32, 4), dim3(32, 8)>>>(Wq, Wk, Wv, Wo);

    // fused QKV GEMM: N = 3072 (Wq^T | Wk^T | Wv^T contiguous)
    gemm_tc<4><<<dim3(3*D_/128, M_/128), 256, GSMEM>>>(
        xhi, xlo, whi, wlo, bq, bk, bv, nullptr);

    attn_tc<<<dim3(S_/64, B_*H_), 128, ATT_SMEM>>>();

    gemm_tc<0><<<dim3(D_/128, M_/128), 256, GSMEM>>>(
        aohi, aolo, whi + 3*(size_t)D_*D_, wlo + 3*(size_t)D_*D_, bo, nullptr, nullptr, out);
}

// round 10
// speedup vs baseline: 3.3853x; 1.0742x over previous
#include <cuda_runtime.h>
#include <cuda_bf16.h>
#include <stdint.h>
#include <math.h>

#define B_  2
#define S_  2048
#define D_  1024
#define H_  16
#define HD_ 64
#define M_  (B_*S_)        // 4096 rows

// ---------------------------------------------------------------------------
// Scratch (__device__ globals; no allocs allowed)
// ---------------------------------------------------------------------------
__device__ __nv_bfloat16 g_qhi[B_*H_*S_*HD_], g_qlo[B_*H_*S_*HD_];   // [B,H,S,HD]
__device__ __nv_bfloat16 g_khi[B_*H_*S_*HD_], g_klo[B_*H_*S_*HD_];
__device__ __nv_bfloat16 g_vhi[B_*H_*S_*HD_], g_vlo[B_*H_*S_*HD_];
__device__ __nv_bfloat16 g_aohi[M_*D_], g_aolo[M_*D_];               // [B,S,D]
__device__ __nv_bfloat16 g_xhi[M_*D_],  g_xlo[M_*D_];                // x split
__device__ __nv_bfloat16 g_whi[4][D_*D_], g_wlo[4][D_*D_];           // W^T splits

// ---------------------------------------------------------------------------
// PTX primitives (all baseline, valid on compute_103)
// ---------------------------------------------------------------------------
__device__ __forceinline__ void mma16816(float* c, const uint32_t* a, const uint32_t* b)
{
    asm volatile("mma.sync.aligned.m16n8k16.row.col.f32.bf16.bf16.f32 "
        "{%0,%1,%2,%3}, {%4,%5,%6,%7}, {%8,%9}, {%0,%1,%2,%3};"
        : "+f"(c[0]), "+f"(c[1]), "+f"(c[2]), "+f"(c[3])
        : "r"(a[0]), "r"(a[1]), "r"(a[2]), "r"(a[3]), "r"(b[0]), "r"(b[1]));
}

__device__ __forceinline__ uint32_t smem_u32(const void* p) {
    uint32_t a;
    asm("{ .reg .u64 t; cvta.to.shared.u64 t, %1; cvt.u32.u64 %0, t; }" : "=r"(a) : "l"(p));
    return a;
}

__device__ __forceinline__ void ldm_x4(uint32_t& r0, uint32_t& r1, uint32_t& r2,
                                       uint32_t& r3, uint32_t addr) {
    asm volatile("ldmatrix.sync.aligned.m8n8.x4.shared.b16 {%0,%1,%2,%3}, [%4];"
        : "=r"(r0), "=r"(r1), "=r"(r2), "=r"(r3) : "r"(addr));
}

__device__ __forceinline__ void cp16(uint32_t s, const void* g) {
    asm volatile("cp.async.cg.shared.global [%0], [%1], 16;" :: "r"(s), "l"(g));
}
#define CP_COMMIT() asm volatile("cp.async.commit_group;" ::: "memory")
#define CP_WAIT1()  asm volatile("cp.async.wait_group 1;" ::: "memory")
#define CP_WAIT0()  asm volatile("cp.async.wait_group 0;" ::: "memory")

// exact-ish splits: rn version (used off hot path)
__device__ __forceinline__ void split2(float v0, float v1, uint32_t& hi, uint32_t& lo) {
    __nv_bfloat16 h0 = __float2bfloat16_rn(v0), h1 = __float2bfloat16_rn(v1);
    __nv_bfloat16 l0 = __float2bfloat16_rn(v0 - __bfloat162float(h0));
    __nv_bfloat16 l1 = __float2bfloat16_rn(v1 - __bfloat162float(h1));
    __nv_bfloat162 h = __nv_bfloat162(h0, h1), l = __nv_bfloat162(l0, l1);
    hi = *(uint32_t*)&h; lo = *(uint32_t*)&l;
}

// fast truncation split: 1 PRMT + 2 AND + 2 FADD + 1 packed CVT
__device__ __forceinline__ void split2t(float v0, float v1, uint32_t& hi, uint32_t& lo) {
    const uint32_t b0 = __float_as_uint(v0), b1 = __float_as_uint(v1);
    uint32_t h;
    asm("prmt.b32 %0, %1, %2, 0x7632;" : "=r"(h) : "r"(b0), "r"(b1));
    const float h0 = __uint_as_float(b0 & 0xffff0000u);
    const float h1 = __uint_as_float(b1 & 0xffff0000u);
    const float l0 = v0 - h0, l1 = v1 - h1;
    uint32_t l;
    asm("cvt.rn.bf16x2.f32 %0, %1, %2;" : "=r"(l) : "f"(l1), "f"(l0));
    hi = h; lo = l;
}

// ---------------------------------------------------------------------------
// Split kernels for the GEMM inputs
// ---------------------------------------------------------------------------
__global__ void split_plain(const float* __restrict__ in, __nv_bfloat16* __restrict__ hi,
                            __nv_bfloat16* __restrict__ lo, int n4)
{
    int i = blockIdx.x * blockDim.x + threadIdx.x;
    if (i >= n4) return;
    float4 a = ((const float4*)in)[i];
    uint32_t h0, l0, h1, l1;
    split2(a.x, a.y, h0, l0);
    split2(a.z, a.w, h1, l1);
    ((uint32_t*)hi)[2*i] = h0; ((uint32_t*)hi)[2*i+1] = h1;
    ((uint32_t*)lo)[2*i] = l0; ((uint32_t*)lo)[2*i+1] = l1;
}

// All 4 weights in one launch: blockIdx.z picks the W; writes g_whi[z]/g_wlo[z].
__global__ void split_transpose4(const float* __restrict__ W0, const float* __restrict__ W1,
                                 const float* __restrict__ W2, const float* __restrict__ W3)
{
    __shared__ float t[32][33];
    const int z = blockIdx.z;
    const float* in = (z == 0) ? W0 : (z == 1) ? W1 : (z == 2) ? W2 : W3;
    __nv_bfloat16* hi = g_whi[z];
    __nv_bfloat16* lo = g_wlo[z];
    const int k0 = blockIdx.y * 32, n0 = blockIdx.x * 32;
    const int tx = threadIdx.x, ty = threadIdx.y;   // 32 x 8
#pragma unroll
    for (int i = 0; i < 32; i += 8)
        t[ty + i][tx] = in[(size_t)(k0 + ty + i) * D_ + n0 + tx];
    __syncthreads();
#pragma unroll
    for (int i = 0; i < 32; i += 8) {
        float a = t[tx][ty + i];
        __nv_bfloat16 h = __float2bfloat16_rn(a);
        __nv_bfloat16 l = __float2bfloat16_rn(a - __bfloat162float(h));
        hi[(size_t)(n0 + ty + i) * D_ + k0 + tx] = h;
        lo[(size_t)(n0 + ty + i) * D_ + k0 + tx] = l;
    }
}

// ---------------------------------------------------------------------------
// HMMA GEMM — single K pass with fused hi/lo (3 MMAs per frag pair).
// Stage = {Ahi, Alo, Bhi, Blo} 128x32 each, LDSG=40 (80B rows, 16B-aligned
// for cp.async — the r9 LDSG=36 layout trapped on misaligned address).
// 2-stage cp.async ring (fits 2 CTAs/SM: 80KB x 2 = 160KB).
// MODE 0: fp32 + bias(b0) -> Cout.
// MODE 4: fused QKV (N=3072); Q pre-scaled by 0.125*log2(e) for exp2 softmax.
// ---------------------------------------------------------------------------
#define LDSG   40
#define GST    (128 * LDSG)                // elems per matrix per stage
#define GSTB   (4 * GST * 2)               // stage bytes (40960)
#define GSMEM  (2 * GSTB)                  // 81920 bytes
#define NKIT   32                          // 1024 / 32

#define QSCALE 0.1803368801111204f         // 0.125 * log2(e)

template<int MODE>
__global__ void __launch_bounds__(256, 2)
gemm_tc(const __nv_bfloat16* __restrict__ Ahi, const __nv_bfloat16* __restrict__ Alo,
        const __nv_bfloat16* __restrict__ Bhi, const __nv_bfloat16* __restrict__ Blo,
        const float* __restrict__ b0, const float* __restrict__ b1,
        const float* __restrict__ b2, float* __restrict__ Cout)
{
    extern __shared__ __nv_bfloat16 sg[];
    const uint32_t smb = smem_u32(sg);

    const int tid  = threadIdx.x;
    const int wid  = tid >> 5, lane = tid & 31;
    const int g    = lane >> 2, t4 = lane & 3;
    const int r8   = lane & 7,  grp = lane >> 3;
    const int wm   = (wid >> 2) * 64;
    const int wn   = (wid & 3) * 32;
    const int bM   = blockIdx.y * 128, bN = blockIdx.x * 128;

    const int rowL = tid >> 1;
    const int colL = (tid & 1) * 16;       // 0 or 16
    const size_t aRow = (size_t)(bM + rowL) * D_;
    const size_t bRow = (size_t)(bN + rowL) * D_;

    const uint32_t sLd = smb + 2u * (rowL * LDSG + colL);

    auto issue = [&](int kc) {
        const uint32_t st = (uint32_t)(kc & 1) * GSTB;
        const size_t k0 = (size_t)kc * 32 + colL;
        const uint32_t s0 = sLd + st;
#pragma unroll
        for (int c = 0; c < 2; c++) {
            cp16(s0 +             c * 16, Ahi + aRow + k0 + c * 8);
            cp16(s0 + 2*GST     + c * 16, Alo + aRow + k0 + c * 8);
            cp16(s0 + 2*GST*2   + c * 16, Bhi + bRow + k0 + c * 8);
            cp16(s0 + 2*GST*3   + c * 16, Blo + bRow + k0 + c * 8);
        }
        CP_COMMIT();
    };

    float acc[4][4][4];
#pragma unroll
    for (int mi = 0; mi < 4; mi++)
#pragma unroll
        for (int ni = 0; ni < 4; ni++)
#pragma unroll
            for (int r = 0; r < 4; r++) acc[mi][ni][r] = 0.f;

    issue(0);
    issue(1);

    for (int kc = 0; kc < NKIT; kc++) {
        CP_WAIT1();            // stage kc landed (stage kc+1 may be in flight)
        __syncthreads();
        const uint32_t stB = smb + (uint32_t)(kc & 1) * GSTB;
        const uint32_t sAh = stB,            sAl = stB + 2*GST;
        const uint32_t sBh = stB + 2*GST*2,  sBl = stB + 2*GST*3;

#pragma unroll
        for (int ks = 0; ks < 2; ks++) {
            const int k0 = ks * 16;
            const int arow = r8 + (grp & 1) * 8;
            const int acol = k0 + (grp >> 1) * 8;
            const int brow = r8 + (grp >> 1) * 8;
            const int bcol = k0 + (grp & 1) * 8;

            uint32_t af[4][4];
#pragma unroll
            for (int mi = 0; mi < 4; mi++)
                ldm_x4(af[mi][0], af[mi][1], af[mi][2], af[mi][3],
                       sAh + 2u * ((wm + mi * 16 + arow) * LDSG + acol));
            uint32_t bfh[4][2], bfl[4][2];
#pragma unroll
            for (int p = 0; p < 2; p++) {
                ldm_x4(bfh[2*p][0], bfh[2*p][1], bfh[2*p+1][0], bfh[2*p+1][1],
                       sBh + 2u * ((wn + p * 16 + brow) * LDSG + bcol));
                ldm_x4(bfl[2*p][0], bfl[2*p][1], bfl[2*p+1][0], bfl[2*p+1][1],
                       sBl + 2u * ((wn + p * 16 + brow) * LDSG + bcol));
            }
#pragma unroll
            for (int mi = 0; mi < 4; mi++)
#pragma unroll
                for (int ni = 0; ni < 4; ni++)
                    mma16816(acc[mi][ni], af[mi], bfh[ni]);
#pragma unroll
            for (int mi = 0; mi < 4; mi++)
#pragma unroll
                for (int ni = 0; ni < 4; ni++)
                    mma16816(acc[mi][ni], af[mi], bfl[ni]);
            // overwrite af with A-lo frags (register reuse)
#pragma unroll
            for (int mi = 0; mi < 4; mi++)
                ldm_x4(af[mi][0], af[mi][1], af[mi][2], af[mi][3],
                       sAl + 2u * ((wm + mi * 16 + arow) * LDSG + acol));
#pragma unroll
            for (int mi = 0; mi < 4; mi++)
#pragma unroll
                for (int ni = 0; ni < 4; ni++)
                    mma16816(acc[mi][ni], af[mi], bfh[ni]);
        }
        // all warps done reading this buffer before it is refilled
        __syncthreads();
        if (kc + 2 < NKIT) issue(kc + 2);
    }

    // ---- epilogue ----
    const float* bias;
    __nv_bfloat16 *Gh = nullptr, *Gl = nullptr;
    int nBase = bN;
    float oscale = 1.f;
    if (MODE == 4) {
        const int which = bN >> 10;
        bias = (which == 0) ? b0 : (which == 1) ? b1 : b2;
        Gh = (which == 0) ? g_qhi : (which == 1) ? g_khi : g_vhi;
        Gl = (which == 0) ? g_qlo : (which == 1) ? g_klo : g_vlo;
        nBase = bN & 1023;
        if (which == 0) oscale = QSCALE;   // fold (1/sqrt(HD))*log2(e) into Q
    } else {
        bias = b0;
    }

#pragma unroll
    for (int mi = 0; mi < 4; mi++) {
#pragma unroll
        for (int hm = 0; hm < 2; hm++) {
            const int m = bM + wm + mi * 16 + g + hm * 8;
#pragma unroll
            for (int ni = 0; ni < 4; ni++) {
                const int nl = nBase + wn + ni * 8 + t4 * 2;
                float v0 = acc[mi][ni][hm * 2 + 0] + bias[nl];
                float v1 = acc[mi][ni][hm * 2 + 1] + bias[nl + 1];
                if (MODE == 0) {
                    *(float2*)(Cout + (size_t)m * D_ + nl) = make_float2(v0, v1);
                } else {
                    v0 *= oscale; v1 *= oscale;
                    const int bb = m >> 11, ss = m & (S_ - 1);
                    const int h = nl >> 6, hd = nl & 63;
                    const size_t o = (((size_t)(bb * H_ + h) * S_ + ss) << 6) + hd;
                    uint32_t hi, lo;
                    split2(v0, v1, hi, lo);
                    *(uint32_t*)(Gh + o) = hi;
                    *(uint32_t*)(Gl + o) = lo;
                }
            }
        }
    }
}

// ---------------------------------------------------------------------------
// Tensor-core flash attention, cp.async double-buffered K/V, 3 CTAs/SM.
// exp2-domain softmax (Q pre-scaled by 0.125*log2e); fast PRMT splits.
// ---------------------------------------------------------------------------
#define PAD 72
#define KVSTAGE (4 * 64 * PAD)            // elems per stage (Khi,Klo,Vhi,Vlo)
#define ATT_SMEM (2 * KVSTAGE * 2)        // 73728 bytes
#define NT (S_ / 64)

__global__ void __launch_bounds__(128, 3)
attn_tc()
{
    extern __shared__ __nv_bfloat16 sm[];
    const uint32_t smb = smem_u32(sm);

    const int tid  = threadIdx.x;
    const int wid  = tid >> 5, lane = tid & 31;
    const int g    = lane >> 2, t4 = lane & 3;
    const int r8   = lane & 7,  grp = lane >> 3;
    const int q0   = blockIdx.x * 64;
    const int bh   = blockIdx.y;
    const int b    = bh >> 4, h = bh & 15;

    const size_t bhOff = (size_t)bh * (S_ * HD_);
    const __nv_bfloat16* Qh = g_qhi + bhOff + (size_t)q0 * HD_;
    const __nv_bfloat16* Ql = g_qlo + bhOff + (size_t)q0 * HD_;
    const __nv_bfloat16* Kh = g_khi + bhOff;
    const __nv_bfloat16* Kl = g_klo + bhOff;
    const __nv_bfloat16* Vh = g_vhi + bhOff;
    const __nv_bfloat16* Vl = g_vlo + bhOff;

    // ---- stage Q (64 rows hi + 64 rows lo; uses stage area, consumed now) ----
#pragma unroll
    for (int i = 0; i < 4; i++) {
        const int idx = tid + i * 128;          // 0..511
        const int row = idx >> 3, c8 = (idx & 7) * 8;
        *(uint4*)&sm[row * PAD + c8]            = *(const uint4*)(Qh + row * HD_ + c8);
        *(uint4*)&sm[64 * PAD + row * PAD + c8] = *(const uint4*)(Ql + row * HD_ + c8);
    }
    __syncthreads();

    uint32_t qh[4][4], ql[4][4];
    {
#pragma unroll
        for (int kc = 0; kc < 4; kc++) {
            const int row = wid * 16 + r8 + (grp & 1) * 8;
            const int col = kc * 16 + (grp >> 1) * 8;
            ldm_x4(qh[kc][0], qh[kc][1], qh[kc][2], qh[kc][3],
                   smb + 2u * (row * PAD + col));
            ldm_x4(ql[kc][0], ql[kc][1], ql[kc][2], ql[kc][3],
                   smb + 2u * (64 * PAD + row * PAD + col));
        }
    }
    __syncthreads();   // Q fully in registers; smem now free for K/V stages

    // per-thread K/V cp.async pattern (128 threads, 64 rows x 8 chunks)
    const int rowKV = tid >> 3, c8KV = (tid & 7) * 8;   // rows 0..15
    auto issueKV = [&](int kt) {
        const uint32_t base = (kt & 1) * KVSTAGE;
#pragma unroll
        for (int i = 0; i < 4; i++) {
            const int row = rowKV + i * 16;
            const size_t gidx = (size_t)(kt * 64 + row) * HD_ + c8KV;
            const uint32_t so = base + row * PAD + c8KV;
            cp16(smb + 2u * so,                 Kh + gidx);
            cp16(smb + 2u * (so +     64*PAD),  Kl + gidx);
            cp16(smb + 2u * (so + 2 * 64*PAD),  Vh + gidx);
            cp16(smb + 2u * (so + 3 * 64*PAD),  Vl + gidx);
        }
        CP_COMMIT();
    };

    float o[8][4];
#pragma unroll
    for (int j = 0; j < 8; j++)
#pragma unroll
        for (int r = 0; r < 4; r++) o[j][r] = 0.f;
    float m0 = -1e30f, m1 = -1e30f, l0 = 0.f, l1 = 0.f;

    issueKV(0);

    for (int kt = 0; kt < NT; kt++) {
        if (kt + 1 < NT) { issueKV(kt + 1); CP_WAIT1(); }
        else             { CP_WAIT0(); }
        __syncthreads();

        const int stB = (kt & 1) * KVSTAGE;
        const int KHI = stB, KLO = stB + 64*PAD, VHI = stB + 2*64*PAD, VLO = stB + 3*64*PAD;

        // ---- S (log2-domain) = Q K^T (3-pass) ----
        float c[8][4];
#pragma unroll
        for (int j = 0; j < 8; j++)
#pragma unroll
            for (int r = 0; r < 4; r++) c[j][r] = 0.f;

#pragma unroll
        for (int kc = 0; kc < 4; kc++) {
#pragma unroll
            for (int p = 0; p < 4; p++) {
                const int row = p * 16 + r8 + (grp >> 1) * 8;
                const int col = kc * 16 + (grp & 1) * 8;
                uint32_t bhA[2], bhB[2], blA[2], blB[2];
                ldm_x4(bhA[0], bhA[1], bhB[0], bhB[1],
                       smb + 2u * (KHI + row * PAD + col));
                ldm_x4(blA[0], blA[1], blB[0], blB[1],
                       smb + 2u * (KLO + row * PAD + col));
                mma16816(c[2*p],   qh[kc], bhA);
                mma16816(c[2*p],   qh[kc], blA);
                mma16816(c[2*p],   ql[kc], bhA);
                mma16816(c[2*p+1], qh[kc], bhB);
                mma16816(c[2*p+1], qh[kc], blB);
                mma16816(c[2*p+1], ql[kc], bhB);
            }
        }

        // ---- online softmax in exp2 domain (rows g, g+8; warp-local quads) ----
        float mx0 = -1e30f, mx1 = -1e30f;
#pragma unroll
        for (int j = 0; j < 8; j++) {
            mx0 = fmaxf(mx0, fmaxf(c[j][0], c[j][1]));
            mx1 = fmaxf(mx1, fmaxf(c[j][2], c[j][3]));
        }
#pragma unroll
        for (int off = 1; off <= 2; off <<= 1) {
            mx0 = fmaxf(mx0, __shfl_xor_sync(0xffffffffu, mx0, off));
            mx1 = fmaxf(mx1, __shfl_xor_sync(0xffffffffu, mx1, off));
        }
        const float nm0 = fmaxf(m0, mx0), nm1 = fmaxf(m1, mx1);
        const float cr0 = exp2f(m0 - nm0), cr1 = exp2f(m1 - nm1);
        float rs0 = 0.f, rs1 = 0.f;
#pragma unroll
        for (int j = 0; j < 8; j++) {
            c[j][0] = exp2f(c[j][0] - nm0);
            c[j][1] = exp2f(c[j][1] - nm0);
            c[j][2] = exp2f(c[j][2] - nm1);
            c[j][3] = exp2f(c[j][3] - nm1);
            rs0 += c[j][0] + c[j][1];
            rs1 += c[j][2] + c[j][3];
        }
#pragma unroll
        for (int off = 1; off <= 2; off <<= 1) {
            rs0 += __shfl_xor_sync(0xffffffffu, rs0, off);
            rs1 += __shfl_xor_sync(0xffffffffu, rs1, off);
        }
        l0 = l0 * cr0 + rs0;  m0 = nm0;
        l1 = l1 * cr1 + rs1;  m1 = nm1;
#pragma unroll
        for (int j = 0; j < 8; j++) {
            o[j][0] *= cr0; o[j][1] *= cr0;
            o[j][2] *= cr1; o[j][3] *= cr1;
        }

        // ---- O += P V (3-pass; P split via fast PRMT; V via ldmatrix.trans) ----
#pragma unroll
        for (int kc = 0; kc < 4; kc++) {
            uint32_t ah[4], al[4];
            split2t(c[2*kc  ][0], c[2*kc  ][1], ah[0], al[0]);
            split2t(c[2*kc  ][2], c[2*kc  ][3], ah[1], al[1]);
            split2t(c[2*kc+1][0], c[2*kc+1][1], ah[2], al[2]);
            split2t(c[2*kc+1][2], c[2*kc+1][3], ah[3], al[3]);

            const int r = lane >> 3, i = lane & 7;
            const int vrow = kc * 16 + (r & 1) * 8 + i;
            const int vcolp = (r >> 1) * 8;

            uint32_t vb[4][4];
#pragma unroll
            for (int np = 0; np < 4; np++) {
                const uint32_t addr = smb + 2u * (uint32_t)(VHI + vrow * PAD + np * 16 + vcolp);
                asm volatile("ldmatrix.sync.aligned.m8n8.x4.trans.shared.b16 {%0,%1,%2,%3}, [%4];"
                    : "=r"(vb[np][0]), "=r"(vb[np][1]), "=r"(vb[np][2]), "=r"(vb[np][3])
                    : "r"(addr));
            }
#pragma unroll
            for (int nt = 0; nt < 8; nt++) {
                uint32_t bb[2] = { vb[nt >> 1][(nt & 1) * 2], vb[nt >> 1][(nt & 1) * 2 + 1] };
                mma16816(o[nt], ah, bb);
                mma16816(o[nt], al, bb);
            }
#pragma unroll
            for (int np = 0; np < 4; np++) {
                const uint32_t addr = smb + 2u * (uint32_t)(VLO + vrow * PAD + np * 16 + vcolp);
                asm volatile("ldmatrix.sync.aligned.m8n8.x4.trans.shared.b16 {%0,%1,%2,%3}, [%4];"
                    : "=r"(vb[np][0]), "=r"(vb[np][1]), "=r"(vb[np][2]), "=r"(vb[np][3])
                    : "r"(addr));
            }
#pragma unroll
            for (int nt = 0; nt < 8; nt++) {
                uint32_t bb[2] = { vb[nt >> 1][(nt & 1) * 2], vb[nt >> 1][(nt & 1) * 2 + 1] };
                mma16816(o[nt], ah, bb);
            }
        }
        __syncthreads();
    }

    // ---- epilogue: normalize, split, write [B,S,D] bf16 hi/lo ----
    const float inv0 = 1.f / l0, inv1 = 1.f / l1;
    const int row0 = q0 + wid * 16 + g;
#pragma unroll
    for (int j = 0; j < 8; j++) {
        const int d = h * HD_ + j * 8 + t4 * 2;
        uint32_t hi, lo;
        split2t(o[j][0] * inv0, o[j][1] * inv0, hi, lo);
        const size_t o0 = (size_t)(b * S_ + row0) * D_ + d;
        *(uint32_t*)(g_aohi + o0) = hi;
        *(uint32_t*)(g_aolo + o0) = lo;
        split2t(o[j][2] * inv1, o[j][3] * inv1, hi, lo);
        const size_t o1 = (size_t)(b * S_ + row0 + 8) * D_ + d;
        *(uint32_t*)(g_aohi + o1) = hi;
        *(uint32_t*)(g_aolo + o1) = lo;
    }
}

// ---------------------------------------------------------------------------

extern "C" void kernel_launch(void* const* d_in, const int* in_sizes, int n_in,
                              void* d_out, int out_size)
{
    const float* x  = (const float*)d_in[0];
    const float* Wq = (const float*)d_in[1];
    const float* bq = (const float*)d_in[2];
    const float* Wk = (const float*)d_in[3];
    const float* bk = (const float*)d_in[4];
    const float* Wv = (const float*)d_in[5];
    const float* bv = (const float*)d_in[6];
    const float* Wo = (const float*)d_in[7];
    const float* bo = (const float*)d_in[8];
    float* out = (float*)d_out;

    void *p_xhi, *p_xlo, *p_aohi, *p_aolo, *p_whi, *p_wlo;
    cudaGetSymbolAddress(&p_xhi,  g_xhi);
    cudaGetSymbolAddress(&p_xlo,  g_xlo);
    cudaGetSymbolAddress(&p_aohi, g_aohi);
    cudaGetSymbolAddress(&p_aolo, g_aolo);
    cudaGetSymbolAddress(&p_whi,  g_whi);
    cudaGetSymbolAddress(&p_wlo,  g_wlo);
    __nv_bfloat16* xhi  = (__nv_bfloat16*)p_xhi;
    __nv_bfloat16* xlo  = (__nv_bfloat16*)p_xlo;
    __nv_bfloat16* aohi = (__nv_bfloat16*)p_aohi;
    __nv_bfloat16* aolo = (__nv_bfloat16*)p_aolo;
    __nv_bfloat16* whi  = (__nv_bfloat16*)p_whi;
    __nv_bfloat16* wlo  = (__nv_bfloat16*)p_wlo;

    cudaFuncSetAttribute(attn_tc,
                         cudaFuncAttributeMaxDynamicSharedMemorySize, ATT_SMEM);
    cudaFuncSetAttribute(gemm_tc<0>, cudaFuncAttributeMaxDynamicSharedMemorySize, GSMEM);
    cudaFuncSetAttribute(gemm_tc<4>, cudaFuncAttributeMaxDynamicSharedMemorySize, GSMEM);

    const int n4 = M_ * D_ / 4;

    split_plain<<<(n4 + 255)/256, 256>>>(x, xhi, xlo, n4);
    split_transpose4<<<dim3(D_/32, D_/32, 4), dim3(32, 8)>>>(Wq, Wk, Wv, Wo);

    // fused QKV GEMM: N = 3072 (Wq^T | Wk^T | Wv^T contiguous)
    gemm_tc<4><<<dim3(3*D_/128, M_/128), 256, GSMEM>>>(
        xhi, xlo, whi, wlo, bq, bk, bv, nullptr);

    attn_tc<<<dim3(S_/64, B_*H_), 128, ATT_SMEM>>>();

    gemm_tc<0><<<dim3(D_/128, M_/128), 256, GSMEM>>>(
        aohi, aolo, whi + 3*(size_t)D_*D_, wlo + 3*(size_t)D_*D_, bo, nullptr, nullptr, out);
}